// round 8
// baseline (speedup 1.0000x reference)
#include <cuda_runtime.h>
#include <cuda_fp16.h>
#include <cstdint>
#include <math.h>

// Problem dims
#define BB 4
#define TT 1024
#define CC 1024
#define HH 16
#define DD 64
#define FF 4096
#define MR 4096   // B*T

// ---------------------------------------------------------------------------
// Scratch (static device globals)
// ---------------------------------------------------------------------------
__device__ __align__(256) float g_proj[MR * CC];
__device__ __align__(256) __half g_qkvH[MR * 3 * CC];
__device__ __align__(256) __half g_qkvL[MR * 3 * CC];
__device__ __align__(256) __half g_hH [MR * CC];
__device__ __align__(256) __half g_hL [MR * CC];
__device__ __align__(256) __half g_atH[MR * CC];
__device__ __align__(256) __half g_atL[MR * CC];
__device__ __align__(256) __half g_h2H[MR * CC];
__device__ __align__(256) __half g_h2L[MR * CC];
__device__ __align__(256) __half g_f1H[MR * FF];
__device__ __align__(256) __half g_f1L[MR * FF];
__device__ __align__(256) __half g_wqH[3 * CC * CC];
__device__ __align__(256) __half g_woH[CC * CC];
__device__ __align__(256) __half g_w1H[FF * CC];
__device__ __align__(256) __half g_w2H[CC * FF];
__device__ int g_mask[MR];
__device__ int g_fu[BB];

// ---------------------------------------------------------------------------
// Helpers
// ---------------------------------------------------------------------------
__device__ __forceinline__ uint32_t smem_u32(const void* p) {
    uint32_t a;
    asm("{ .reg .u64 t; cvta.to.shared.u64 t, %1; cvt.u32.u64 %0, t; }" : "=r"(a) : "l"(p));
    return a;
}
__device__ __forceinline__ void cp16(uint32_t s, const void* g) {
    asm volatile("cp.async.cg.shared.global [%0], [%1], 16;" :: "r"(s), "l"(g));
}
#define CP_COMMIT() asm volatile("cp.async.commit_group;" ::: "memory")
#define CP_WAIT2()  asm volatile("cp.async.wait_group 2;"  ::: "memory")
#define CP_WAIT1()  asm volatile("cp.async.wait_group 1;"  ::: "memory")
#define CP_WAIT0()  asm volatile("cp.async.wait_group 0;"  ::: "memory")

#define LDSM4(r, addr) \
    asm volatile("ldmatrix.sync.aligned.m8n8.x4.shared.b16 {%0,%1,%2,%3}, [%4];" \
        : "=r"((r)[0]), "=r"((r)[1]), "=r"((r)[2]), "=r"((r)[3]) : "r"(addr))
#define LDSM4T(r, addr) \
    asm volatile("ldmatrix.sync.aligned.m8n8.x4.trans.shared.b16 {%0,%1,%2,%3}, [%4];" \
        : "=r"((r)[0]), "=r"((r)[1]), "=r"((r)[2]), "=r"((r)[3]) : "r"(addr))

// fp32-accumulate mma
__device__ __forceinline__ void mma16816(float* c, const uint32_t* a, const uint32_t* b) {
    asm volatile("mma.sync.aligned.m16n8k16.row.col.f32.f16.f16.f32 "
        "{%0,%1,%2,%3}, {%4,%5,%6,%7}, {%8,%9}, {%0,%1,%2,%3};"
        : "+f"(c[0]), "+f"(c[1]), "+f"(c[2]), "+f"(c[3])
        : "r"(a[0]), "r"(a[1]), "r"(a[2]), "r"(a[3]), "r"(b[0]), "r"(b[1]));
}
// fp16-accumulate mma (2x rate; used only for ~2^-12-scale correction terms)
__device__ __forceinline__ void mma16816h(uint32_t* c, const uint32_t* a, const uint32_t* b) {
    asm volatile("mma.sync.aligned.m16n8k16.row.col.f16.f16.f16.f16 "
        "{%0,%1}, {%2,%3,%4,%5}, {%6,%7}, {%0,%1};"
        : "+r"(c[0]), "+r"(c[1])
        : "r"(a[0]), "r"(a[1]), "r"(a[2]), "r"(a[3]), "r"(b[0]), "r"(b[1]));
}
__device__ __forceinline__ void fold_h2(float* f, const uint32_t* h) {
    __half2 c0 = *(const __half2*)&h[0];
    __half2 c1 = *(const __half2*)&h[1];
    f[0] += __low2float(c0); f[1] += __high2float(c0);
    f[2] += __low2float(c1); f[3] += __high2float(c1);
}

__device__ __forceinline__ void split2(float v, __half& h, __half& l) {
    h = __float2half_rn(v);
    l = __float2half_rn(v - __half2float(h));
}
__device__ __forceinline__ float fex2(float x) {
    float r;
    asm("ex2.approx.ftz.f32 %0, %1;" : "=f"(r) : "f"(x));
    return r;
}

// ---------------------------------------------------------------------------
// Mask classify + expand + first-unpadded per batch
// ---------------------------------------------------------------------------
__global__ void mask_expand_kernel(const void* __restrict__ pm, int* __restrict__ out)
{
    int tid = threadIdx.x;
    if (tid < BB) g_fu[tid] = TT;
    const unsigned* w = (const unsigned*)pm;
    int li = 0, lf = 0;
    for (int i = tid; i < 1024; i += 256) {
        unsigned v = w[i];
        li |= (v > 1u);
        lf |= (v != 0u && v != 0x3F800000u);
    }
    int not_int = __syncthreads_or(li);
    int not_flt = __syncthreads_or(lf);
    int cls = (!not_int) ? 0 : ((!not_flt) ? 1 : 2);
    for (int i = tid; i < MR; i += 256) {
        int m;
        if (cls == 0)      m = (((const int*)pm)[i] != 0);
        else if (cls == 1) m = (((const float*)pm)[i] != 0.0f);
        else               m = (((const unsigned char*)pm)[i] != 0);
        out[i] = m;
        if (!m) atomicMin(&g_fu[i >> 10], i & 1023);
    }
}

// ---------------------------------------------------------------------------
// Pack Wq/Wk/Wv (H,C,D) -> transposed (3C, C) fp16
// ---------------------------------------------------------------------------
__global__ void pack_qkv_kernel(const float* __restrict__ Wq,
                                const float* __restrict__ Wk,
                                const float* __restrict__ Wv,
                                __half* __restrict__ oh)
{
    int idx = blockIdx.x * blockDim.x + threadIdx.x;
    if (idx >= 3 * CC * CC) return;
    int j = idx / CC;
    int c = idx % CC;
    const float* W = (j < CC) ? Wq : (j < 2 * CC) ? Wk : Wv;
    int jj = j & (CC - 1);
    int h = jj >> 6, d = jj & 63;
    oh[idx] = __float2half_rn(W[(h * CC + c) * DD + d]);
}

// ---------------------------------------------------------------------------
// Tiled transpose: in (R, Cn) fp32 -> out (Cn, R) fp16
// ---------------------------------------------------------------------------
__global__ void tsplit_kernel(const float* __restrict__ in,
                              __half* __restrict__ oh,
                              int R, int Cn)
{
    __shared__ float t[32][33];
    int c0 = blockIdx.x * 32, r0 = blockIdx.y * 32;
    int x = threadIdx.x, y = threadIdx.y;
#pragma unroll
    for (int i = 0; i < 32; i += 8)
        t[y + i][x] = in[(size_t)(r0 + y + i) * Cn + c0 + x];
    __syncthreads();
#pragma unroll
    for (int i = 0; i < 32; i += 8)
        oh[(size_t)(c0 + y + i) * R + r0 + x] = __float2half_rn(t[x][y + i]);
}

// ---------------------------------------------------------------------------
// LayerNorm + split (fp16 hi/lo)
// ---------------------------------------------------------------------------
__global__ __launch_bounds__(256) void ln_split_kernel(const float* __restrict__ x,
                                                       const float* __restrict__ g,
                                                       const float* __restrict__ b,
                                                       __half* __restrict__ oh,
                                                       __half* __restrict__ ol)
{
    int row = blockIdx.x, tid = threadIdx.x;
    const float* xr = x + (size_t)row * CC;
    float v[4];
    float s = 0.f, ss = 0.f;
#pragma unroll
    for (int i = 0; i < 4; i++) {
        v[i] = xr[tid + i * 256];
        s += v[i];
        ss += v[i] * v[i];
    }
#pragma unroll
    for (int o = 16; o; o >>= 1) {
        s  += __shfl_xor_sync(0xffffffffu, s,  o);
        ss += __shfl_xor_sync(0xffffffffu, ss, o);
    }
    __shared__ float ws[8], wss[8];
    __shared__ float s_m, s_r;
    int wid = tid >> 5;
    if ((tid & 31) == 0) { ws[wid] = s; wss[wid] = ss; }
    __syncthreads();
    if (tid == 0) {
        float S = 0.f, SS = 0.f;
        for (int i = 0; i < 8; i++) { S += ws[i]; SS += wss[i]; }
        float m = S * (1.0f / CC);
        float var = SS * (1.0f / CC) - m * m;
        s_m = m;
        s_r = rsqrtf(var + 1e-5f);
    }
    __syncthreads();
    float m = s_m, r = s_r;
#pragma unroll
    for (int i = 0; i < 4; i++) {
        int c = tid + i * 256;
        float o = (v[i] - m) * r * g[c] + b[c];
        __half hh, ll; split2(o, hh, ll);
        size_t idx = (size_t)row * CC + c;
        oh[idx] = hh; ol[idx] = ll;
    }
}

// ---------------------------------------------------------------------------
// fp16 GEMM v3: D = (Ah+Al)(M,K) @ Bh^T, B stored (N,K) fp16.
// CTA 128x256, 512 threads / 16 warps (warp tile 64x32), K-chunk 64,
// 3-stage cp.async pipeline.
// Main pass Ah·Bh: fp32 accumulate. Correction pass Al·Bh: fp16 accumulate
// (2x tensor rate; terms are ~2^-12 of main so fp16 accumulation is safe),
// folded into the fp32 accumulator at the end.
// ---------------------------------------------------------------------------
#define PITCH 72
#define A_TILE_B (128 * PITCH * 2)          // 18432
#define B_TILE_B (256 * PITCH * 2)          // 36864
#define STAGE_B (2 * A_TILE_B + B_TILE_B)   // 73728
#define NSTAGE 3
#define GEMM_SMEM (NSTAGE * STAGE_B)        // 221184

__global__ __launch_bounds__(512, 1) void gemm_mma(
    const __half* __restrict__ Ah, const __half* __restrict__ Al,
    const __half* __restrict__ Bh,
    const float* __restrict__ bias,
    float* __restrict__ outF,
    __half* __restrict__ outH, __half* __restrict__ outL,
    int Ntot, int Ktot, int relu)
{
    extern __shared__ __align__(128) char smem[];
    const uint32_t sb0 = smem_u32(smem);
    int tid = threadIdx.x, lane = tid & 31, w = tid >> 5;
    int bm = blockIdx.y * 128, bn = blockIdx.x * 256;
    int wm = (w >> 3) * 64, wn = (w & 7) * 32;
    int nk = Ktot >> 6;

    float facc[4][4][4];
    uint32_t hacc[4][4][2];
#pragma unroll
    for (int i = 0; i < 4; i++)
#pragma unroll
        for (int j = 0; j < 4; j++) {
#pragma unroll
            for (int e = 0; e < 4; e++) facc[i][j][e] = 0.0f;
            hacc[i][j][0] = 0u; hacc[i][j][1] = 0u;
        }

    auto load_stage = [&](int st, int kc) {
        uint32_t sb = sb0 + st * STAGE_B;
#pragma unroll
        for (int i = 0; i < 8; i++) {
            int idx = tid + i * 512;          // 0..4095
            int c = (idx & 7) * 8;
            if (idx < 1024) {                 // Ah
                int r = idx >> 3;
                cp16(sb + (uint32_t)(r * PITCH + c) * 2,
                     Ah + (size_t)(bm + r) * Ktot + kc + c);
            } else if (idx < 2048) {          // Al
                int r = (idx - 1024) >> 3;
                cp16(sb + A_TILE_B + (uint32_t)(r * PITCH + c) * 2,
                     Al + (size_t)(bm + r) * Ktot + kc + c);
            } else {                          // Bh
                int r = (idx - 2048) >> 3;
                cp16(sb + 2 * A_TILE_B + (uint32_t)(r * PITCH + c) * 2,
                     Bh + (size_t)(bn + r) * Ktot + kc + c);
            }
        }
    };

    load_stage(0, 0);
    CP_COMMIT();
    if (nk > 1) { load_stage(1, 64); CP_COMMIT(); }

    int lrow = lane & 15;
    int lk = (lane >> 4) * 8;

    for (int kc = 0; kc < nk; kc++) {
        if (kc + 2 < nk) {
            load_stage((kc + 2) % 3, (kc + 2) * 64);
            CP_COMMIT();
            CP_WAIT2();
        } else {
            CP_WAIT0();
        }
        __syncthreads();

        uint32_t sb = sb0 + (kc % 3) * STAGE_B;
#pragma unroll
        for (int ks = 0; ks < 4; ks++) {
            int k0 = ks * 16;
            uint32_t ah[4][4], al[4][4], bh[4][2];
#pragma unroll
            for (int i = 0; i < 4; i++) {
                uint32_t ad = sb + (uint32_t)((wm + i * 16 + lrow) * PITCH + k0 + lk) * 2;
                LDSM4(ah[i], ad);
                LDSM4(al[i], ad + A_TILE_B);
            }
#pragma unroll
            for (int jj = 0; jj < 2; jj++) {
                uint32_t bd = sb + 2 * A_TILE_B +
                              (uint32_t)((wn + jj * 16 + lrow) * PITCH + k0 + lk) * 2;
                uint32_t t[4];
                LDSM4(t, bd);
                bh[jj * 2][0] = t[0]; bh[jj * 2][1] = t[2];
                bh[jj * 2 + 1][0] = t[1]; bh[jj * 2 + 1][1] = t[3];
            }
#pragma unroll
            for (int i = 0; i < 4; i++)
#pragma unroll
                for (int j = 0; j < 4; j++)
                    mma16816(facc[i][j], ah[i], bh[j]);
#pragma unroll
            for (int i = 0; i < 4; i++)
#pragma unroll
                for (int j = 0; j < 4; j++)
                    mma16816h(hacc[i][j], al[i], bh[j]);
        }
        __syncthreads();
    }

    // fold fp16 correction accumulators into fp32
#pragma unroll
    for (int i = 0; i < 4; i++)
#pragma unroll
        for (int j = 0; j < 4; j++)
            fold_h2(facc[i][j], hacc[i][j]);

#pragma unroll
    for (int i = 0; i < 4; i++) {
        int r0 = bm + wm + i * 16 + (lane >> 2);
#pragma unroll
        for (int j = 0; j < 4; j++) {
            int c = bn + wn + j * 8 + (lane & 3) * 2;
            float bx0 = bias ? bias[c] : 0.0f;
            float bx1 = bias ? bias[c + 1] : 0.0f;
#pragma unroll
            for (int hh = 0; hh < 2; hh++) {
                int r = r0 + hh * 8;
                float v0 = facc[i][j][hh * 2 + 0] + bx0;
                float v1 = facc[i][j][hh * 2 + 1] + bx1;
                if (relu) { v0 = fmaxf(v0, 0.0f); v1 = fmaxf(v1, 0.0f); }
                size_t o = (size_t)r * Ntot + c;
                if (outF) {
                    outF[o] = v0;
                    outF[o + 1] = v1;
                } else {
                    __half h0, l0, h1, l1;
                    split2(v0, h0, l0);
                    split2(v1, h1, l1);
                    __half2 hp; hp.x = h0; hp.y = h1;
                    __half2 lp; lp.x = l0; lp.y = l1;
                    *(__half2*)(outH + o) = hp;
                    *(__half2*)(outL + o) = lp;
                }
            }
        }
    }
}

// ---------------------------------------------------------------------------
// fp16 flash attention (corrections in fp16 accumulate)
// ---------------------------------------------------------------------------
#define AT_PITCH 72
#define AQ_TILEB (128 * AT_PITCH * 2)     // 18432
#define AKV_TILEB (64 * AT_PITCH * 2)     // 9216
#define SMASK_OFF (2 * AQ_TILEB + 4 * AKV_TILEB)   // 73728
#define ATT_SMEM (SMASK_OFF + 2 * 64 * 4)          // 74240

__global__ __launch_bounds__(256) void attn_mma(
    const __half* __restrict__ qkvH,
    const __half* __restrict__ qkvL,
    const int* __restrict__ mask,
    __half* __restrict__ outH,
    __half* __restrict__ outL)
{
    extern __shared__ __align__(128) char smem[];
    const uint32_t sb = smem_u32(smem);
    const uint32_t sQh = sb, sQl = sb + AQ_TILEB;

    int qi = (int)gridDim.x - 1 - (int)blockIdx.x;   // heavy blocks first
    int bh = blockIdx.y;
    int b = bh >> 4, h = bh & 15;
    int tid = threadIdx.x, lane = tid & 31, w = tid >> 5;
    int wq = w * 16;
    int lrow = lane & 15, lkc = (lane >> 4) * 8;

    const size_t rowbase = (size_t)(b * TT) * (3 * CC) + h * DD;
    const int* gmask = mask + b * TT;
    int* smask = (int*)(smem + SMASK_OFF);

    // Q tile (hi+lo)
#pragma unroll
    for (int i = 0; i < 4; i++) {
        int idx = tid + i * 256;
        int r = idx >> 3, ch = (idx & 7) * 8;
        uint32_t so = (uint32_t)(r * AT_PITCH + ch) * 2;
        size_t go = rowbase + (size_t)(qi * 128 + r) * (3 * CC) + ch;
        cp16(sQh + so, qkvH + go);
        cp16(sQl + so, qkvL + go);
    }

    auto load_stage = [&](int sj) {
        int st = sj & 1;
        uint32_t base = sb + 2 * AQ_TILEB + st * (2 * AKV_TILEB);
#pragma unroll
        for (int i = 0; i < 4; i++) {
            int idx = tid + i * 256;
            int tile = idx >> 9;
            int rem = idx & 511;
            int r = rem >> 3, ch = (rem & 7) * 8;
            uint32_t so = base + tile * AKV_TILEB + (uint32_t)(r * AT_PITCH + ch) * 2;
            size_t gk = rowbase + (size_t)(sj * 64 + r) * (3 * CC) + CC + ch;
            if (tile == 0) cp16(so, qkvH + gk);
            else           cp16(so, qkvH + gk + CC);
        }
        if (tid < 16)
            cp16(sb + SMASK_OFF + st * 256 + tid * 16, gmask + sj * 64 + tid * 4);
    };

    int ns = 2 * qi + 2;
    load_stage(0);
    CP_COMMIT();

    float O[8][4];
    uint32_t hO[8][2];
#pragma unroll
    for (int j = 0; j < 8; j++) {
#pragma unroll
        for (int e = 0; e < 4; e++) O[j][e] = 0.0f;
        hO[j][0] = 0u; hO[j][1] = 0u;
    }
    float lsum0 = 0.0f, lsum1 = 0.0f;

    const float csc = 0.0450842200f;   // log2(e) / 32
    const int t_base = qi * 128 + wq + (lane >> 2);

    for (int sj = 0; sj < ns; sj++) {
        int cur = sj & 1;
        if (sj + 1 < ns) {
            load_stage(sj + 1);
            CP_COMMIT();
            CP_WAIT1();
        } else {
            CP_WAIT0();
        }
        __syncthreads();

        uint32_t kvb = sb + 2 * AQ_TILEB + cur * (2 * AKV_TILEB);
        uint32_t sKh = kvb, sVh = kvb + AKV_TILEB;
        const int* mrow = smask + cur * 64;

        // S = Q K^T: main f32-acc pass + f16-acc correction
        float S[8][4];
        uint32_t hS[8][2];
#pragma unroll
        for (int j = 0; j < 8; j++) {
#pragma unroll
            for (int e = 0; e < 4; e++) S[j][e] = 0.0f;
            hS[j][0] = 0u; hS[j][1] = 0u;
        }

#pragma unroll
        for (int ks = 0; ks < 4; ks++) {
            uint32_t qa[4], ql[4];
            uint32_t ad = sQh + (uint32_t)((wq + lrow) * AT_PITCH + ks * 16 + lkc) * 2;
            LDSM4(qa, ad);
            LDSM4(ql, ad + AQ_TILEB);
#pragma unroll
            for (int nj = 0; nj < 4; nj++) {
                uint32_t bd = sKh + (uint32_t)((nj * 16 + lrow) * AT_PITCH + ks * 16 + lkc) * 2;
                uint32_t th[4];
                LDSM4(th, bd);
                uint32_t bh0[2] = {th[0], th[2]}, bh1[2] = {th[1], th[3]};
                mma16816(S[2 * nj],     qa, bh0);
                mma16816(S[2 * nj + 1], qa, bh1);
                mma16816h(hS[2 * nj],     ql, bh0);
                mma16816h(hS[2 * nj + 1], ql, bh1);
            }
        }

        // fold correction + mask + exp2
#pragma unroll
        for (int j = 0; j < 8; j++) {
            fold_h2(S[j], hS[j]);
            int s0 = j * 8 + (lane & 3) * 2;
#pragma unroll
            for (int e = 0; e < 4; e++) {
                int s_l = s0 + (e & 1);
                int s_g = sj * 64 + s_l;
                int t_g = t_base + (e >> 1) * 8;
                float v = S[j][e] * csc;
                if (mrow[s_l] || (s_g > t_g)) v = -1e9f;
                S[j][e] = fex2(v);
            }
            lsum0 += S[j][0] + S[j][1];
            lsum1 += S[j][2] + S[j][3];
        }

        // pack P (hi/lo fp16)
        uint32_t aPh[8][2], aPl[8][2];
#pragma unroll
        for (int j = 0; j < 8; j++) {
            __half2 h0 = __floats2half2_rn(S[j][0], S[j][1]);
            __half2 h1 = __floats2half2_rn(S[j][2], S[j][3]);
            float r00 = S[j][0] - __half2float(h0.x);
            float r01 = S[j][1] - __half2float(h0.y);
            float r10 = S[j][2] - __half2float(h1.x);
            float r11 = S[j][3] - __half2float(h1.y);
            __half2 l0 = __floats2half2_rn(r00, r01);
            __half2 l1 = __floats2half2_rn(r10, r11);
            aPh[j][0] = *(uint32_t*)&h0; aPh[j][1] = *(uint32_t*)&h1;
            aPl[j][0] = *(uint32_t*)&l0; aPl[j][1] = *(uint32_t*)&l1;
        }

        // O += P V: main f32-acc + f16-acc correction
#pragma unroll
        for (int kc = 0; kc < 4; kc++) {
            uint32_t Ahf[4] = {aPh[2 * kc][0], aPh[2 * kc][1],
                               aPh[2 * kc + 1][0], aPh[2 * kc + 1][1]};
            uint32_t Alf[4] = {aPl[2 * kc][0], aPl[2 * kc][1],
                               aPl[2 * kc + 1][0], aPl[2 * kc + 1][1]};
#pragma unroll
            for (int dj = 0; dj < 4; dj++) {
                uint32_t vd = sVh + (uint32_t)((kc * 16 + lrow) * AT_PITCH + dj * 16 + lkc) * 2;
                uint32_t tvh[4];
                LDSM4T(tvh, vd);
                uint32_t bh0[2] = {tvh[0], tvh[1]}, bh1[2] = {tvh[2], tvh[3]};
                mma16816(O[2 * dj],     Ahf, bh0);
                mma16816(O[2 * dj + 1], Ahf, bh1);
                mma16816h(hO[2 * dj],     Alf, bh0);
                mma16816h(hO[2 * dj + 1], Alf, bh1);
            }
        }
        __syncthreads();
    }

    // finalize: fold corrections, reduce l, normalize, write split fp16
#pragma unroll
    for (int j = 0; j < 8; j++) fold_h2(O[j], hO[j]);

    lsum0 += __shfl_xor_sync(0xffffffffu, lsum0, 1);
    lsum0 += __shfl_xor_sync(0xffffffffu, lsum0, 2);
    lsum1 += __shfl_xor_sync(0xffffffffu, lsum1, 1);
    lsum1 += __shfl_xor_sync(0xffffffffu, lsum1, 2);
    float inv0 = 1.0f / lsum0;
    float inv1 = 1.0f / lsum1;

#pragma unroll
    for (int hh = 0; hh < 2; hh++) {
        float inv = hh ? inv1 : inv0;
        size_t orow = (size_t)(b * TT + t_base + hh * 8) * CC + h * DD + (lane & 3) * 2;
#pragma unroll
        for (int j = 0; j < 8; j++) {
            float v0 = O[j][hh * 2 + 0] * inv;
            float v1 = O[j][hh * 2 + 1] * inv;
            __half h0, l0, h1, l1;
            split2(v0, h0, l0);
            split2(v1, h1, l1);
            __half2 hp; hp.x = h0; hp.y = h1;
            __half2 lp; lp.x = l0; lp.y = l1;
            *(__half2*)(outH + orow + j * 8) = hp;
            *(__half2*)(outL + orow + j * 8) = lp;
        }
    }
}

// ---------------------------------------------------------------------------
// Fixup: rows t < first_unpadded[b] -> out = mean of V over padded positions.
// ---------------------------------------------------------------------------
__global__ __launch_bounds__(256) void fixup_kernel(
    const __half* __restrict__ qkvH,
    const __half* __restrict__ qkvL,
    const int* __restrict__ mask,
    __half* __restrict__ outH,
    __half* __restrict__ outL)
{
    int b = blockIdx.x;
    int f = g_fu[b];
    if (f == 0) return;
    int tid = threadIdx.x;
    float sum[4] = {0, 0, 0, 0};
    int cnt = 0;
    for (int s = 0; s < TT; s++) {
        if (mask[b * TT + s]) {
            cnt++;
            size_t base = (size_t)(b * TT + s) * (3 * CC) + 2 * CC + tid * 4;
#pragma unroll
            for (int e = 0; e < 4; e++)
                sum[e] += __half2float(qkvH[base + e]) +
                          __half2float(qkvL[base + e]);
        }
    }
    float invc = 1.0f / (float)cnt;
    __half mh[4], ml[4];
#pragma unroll
    for (int e = 0; e < 4; e++) split2(sum[e] * invc, mh[e], ml[e]);
    for (int t = 0; t < f; t++) {
        size_t o = (size_t)(b * TT + t) * CC + tid * 4;
#pragma unroll
        for (int e = 0; e < 4; e++) {
            outH[o + e] = mh[e];
            outL[o + e] = ml[e];
        }
    }
}

// ---------------------------------------------------------------------------
// Launch
// ---------------------------------------------------------------------------
extern "C" void kernel_launch(void* const* d_in, const int* in_sizes, int n_in,
                              void* d_out, int out_size)
{
    const float* x     = (const float*)d_in[0];
    const void*  pmask = d_in[1];
    const float* Wq    = (const float*)d_in[2];
    const float* Wk    = (const float*)d_in[3];
    const float* Wv    = (const float*)d_in[4];
    const float* Wo    = (const float*)d_in[5];
    const float* bo    = (const float*)d_in[6];
    const float* ln1_g = (const float*)d_in[7];
    const float* ln1_b = (const float*)d_in[8];
    const float* ln2_g = (const float*)d_in[9];
    const float* ln2_b = (const float*)d_in[10];
    const float* W1    = (const float*)d_in[11];
    const float* b1    = (const float*)d_in[12];
    const float* W2    = (const float*)d_in[13];
    const float* b2    = (const float*)d_in[14];
    float* out = (float*)d_out;

    void *p_proj, *p_qkvH, *p_qkvL, *p_hH, *p_hL, *p_atH, *p_atL,
         *p_h2H, *p_h2L, *p_f1H, *p_f1L, *p_wqH, *p_woH, *p_w1H, *p_w2H, *p_mask;
    cudaGetSymbolAddress(&p_proj, g_proj);
    cudaGetSymbolAddress(&p_qkvH, g_qkvH);
    cudaGetSymbolAddress(&p_qkvL, g_qkvL);
    cudaGetSymbolAddress(&p_hH,   g_hH);
    cudaGetSymbolAddress(&p_hL,   g_hL);
    cudaGetSymbolAddress(&p_atH,  g_atH);
    cudaGetSymbolAddress(&p_atL,  g_atL);
    cudaGetSymbolAddress(&p_h2H,  g_h2H);
    cudaGetSymbolAddress(&p_h2L,  g_h2L);
    cudaGetSymbolAddress(&p_f1H,  g_f1H);
    cudaGetSymbolAddress(&p_f1L,  g_f1L);
    cudaGetSymbolAddress(&p_wqH,  g_wqH);
    cudaGetSymbolAddress(&p_woH,  g_woH);
    cudaGetSymbolAddress(&p_w1H,  g_w1H);
    cudaGetSymbolAddress(&p_w2H,  g_w2H);
    cudaGetSymbolAddress(&p_mask, g_mask);

    cudaFuncSetAttribute(gemm_mma, cudaFuncAttributeMaxDynamicSharedMemorySize, GEMM_SMEM);
    cudaFuncSetAttribute(attn_mma, cudaFuncAttributeMaxDynamicSharedMemorySize, ATT_SMEM);

    // 1. mask + first-unpadded
    mask_expand_kernel<<<1, 256>>>(pmask, (int*)p_mask);
    // 2. weight prep (fp16)
    pack_qkv_kernel<<<(3 * CC * CC + 255) / 256, 256>>>(Wq, Wk, Wv, (__half*)p_wqH);
    tsplit_kernel<<<dim3(CC / 32, CC / 32), dim3(32, 8)>>>(Wo, (__half*)p_woH, CC, CC);
    tsplit_kernel<<<dim3(FF / 32, CC / 32), dim3(32, 8)>>>(W1, (__half*)p_w1H, CC, FF);
    tsplit_kernel<<<dim3(CC / 32, FF / 32), dim3(32, 8)>>>(W2, (__half*)p_w2H, FF, CC);
    // 3. LN1
    ln_split_kernel<<<MR, 256>>>(x, ln1_g, ln1_b, (__half*)p_hH, (__half*)p_hL);
    // 4. QKV gemm
    gemm_mma<<<dim3(3 * CC / 256, MR / 128), 512, GEMM_SMEM>>>(
        (__half*)p_hH, (__half*)p_hL, (__half*)p_wqH, nullptr,
        nullptr, (__half*)p_qkvH, (__half*)p_qkvL, 3 * CC, CC, 0);
    // 5. flash attention + fixup
    attn_mma<<<dim3(TT / 128, BB * HH), 256, ATT_SMEM>>>(
        (const __half*)p_qkvH, (const __half*)p_qkvL, (const int*)p_mask,
        (__half*)p_atH, (__half*)p_atL);
    fixup_kernel<<<BB, 256>>>(
        (const __half*)p_qkvH, (const __half*)p_qkvL, (const int*)p_mask,
        (__half*)p_atH, (__half*)p_atL);
    // 6. Wo projection
    gemm_mma<<<dim3(CC / 256, MR / 128), 512, GEMM_SMEM>>>(
        (__half*)p_atH, (__half*)p_atL, (__half*)p_woH, bo,
        (float*)p_proj, nullptr, nullptr, CC, CC, 0);
    // 7. LN2
    ln_split_kernel<<<MR, 256>>>((const float*)p_proj, ln2_g, ln2_b,
                                 (__half*)p_h2H, (__half*)p_h2L);
    // 8. FFN1 + relu
    gemm_mma<<<dim3(FF / 256, MR / 128), 512, GEMM_SMEM>>>(
        (__half*)p_h2H, (__half*)p_h2L, (__half*)p_w1H, b1,
        nullptr, (__half*)p_f1H, (__half*)p_f1L, FF, CC, 1);
    // 9. FFN2 -> d_out
    gemm_mma<<<dim3(CC / 256, MR / 128), 512, GEMM_SMEM>>>(
        (__half*)p_f1H, (__half*)p_f1L, (__half*)p_w2H, b2,
        out, nullptr, nullptr, CC, FF, 0);
}

// round 9
// speedup vs baseline: 1.3070x; 1.3070x over previous
#include <cuda_runtime.h>
#include <cuda_fp16.h>
#include <cstdint>
#include <math.h>

// Problem dims
#define BB 4
#define TT 1024
#define CC 1024
#define HH 16
#define DD 64
#define FF 4096
#define MR 4096   // B*T

// ---------------------------------------------------------------------------
// Scratch (static device globals)
// ---------------------------------------------------------------------------
__device__ __align__(256) float g_proj[MR * CC];
__device__ __align__(256) __half g_qkvH[MR * 3 * CC];
__device__ __align__(256) __half g_qkvL[MR * 3 * CC];
__device__ __align__(256) __half g_hH [MR * CC];
__device__ __align__(256) __half g_hL [MR * CC];
__device__ __align__(256) __half g_atH[MR * CC];
__device__ __align__(256) __half g_atL[MR * CC];
__device__ __align__(256) __half g_h2H[MR * CC];
__device__ __align__(256) __half g_h2L[MR * CC];
__device__ __align__(256) __half g_f1H[MR * FF];
__device__ __align__(256) __half g_wqH[3 * CC * CC];
__device__ __align__(256) __half g_woH[CC * CC];
__device__ __align__(256) __half g_w1H[FF * CC];
__device__ __align__(256) __half g_w2H[CC * FF];
__device__ int g_mask[MR];
__device__ int g_fu[BB];

// ---------------------------------------------------------------------------
// Helpers
// ---------------------------------------------------------------------------
__device__ __forceinline__ uint32_t smem_u32(const void* p) {
    uint32_t a;
    asm("{ .reg .u64 t; cvta.to.shared.u64 t, %1; cvt.u32.u64 %0, t; }" : "=r"(a) : "l"(p));
    return a;
}
__device__ __forceinline__ void cp16(uint32_t s, const void* g) {
    asm volatile("cp.async.cg.shared.global [%0], [%1], 16;" :: "r"(s), "l"(g));
}
#define CP_COMMIT() asm volatile("cp.async.commit_group;" ::: "memory")
#define CP_WAIT2()  asm volatile("cp.async.wait_group 2;"  ::: "memory")
#define CP_WAIT1()  asm volatile("cp.async.wait_group 1;"  ::: "memory")
#define CP_WAIT0()  asm volatile("cp.async.wait_group 0;"  ::: "memory")

#define LDSM4(r, addr) \
    asm volatile("ldmatrix.sync.aligned.m8n8.x4.shared.b16 {%0,%1,%2,%3}, [%4];" \
        : "=r"((r)[0]), "=r"((r)[1]), "=r"((r)[2]), "=r"((r)[3]) : "r"(addr))
#define LDSM4T(r, addr) \
    asm volatile("ldmatrix.sync.aligned.m8n8.x4.trans.shared.b16 {%0,%1,%2,%3}, [%4];" \
        : "=r"((r)[0]), "=r"((r)[1]), "=r"((r)[2]), "=r"((r)[3]) : "r"(addr))

__device__ __forceinline__ void mma16816(float* c, const uint32_t* a, const uint32_t* b) {
    asm volatile("mma.sync.aligned.m16n8k16.row.col.f32.f16.f16.f32 "
        "{%0,%1,%2,%3}, {%4,%5,%6,%7}, {%8,%9}, {%0,%1,%2,%3};"
        : "+f"(c[0]), "+f"(c[1]), "+f"(c[2]), "+f"(c[3])
        : "r"(a[0]), "r"(a[1]), "r"(a[2]), "r"(a[3]), "r"(b[0]), "r"(b[1]));
}

__device__ __forceinline__ void split2(float v, __half& h, __half& l) {
    h = __float2half_rn(v);
    l = __float2half_rn(v - __half2float(h));
}
__device__ __forceinline__ float fex2(float x) {
    float r;
    asm("ex2.approx.ftz.f32 %0, %1;" : "=f"(r) : "f"(x));
    return r;
}

// ---------------------------------------------------------------------------
// Mask classify + expand + first-unpadded per batch
// ---------------------------------------------------------------------------
__global__ void mask_expand_kernel(const void* __restrict__ pm, int* __restrict__ out)
{
    int tid = threadIdx.x;
    if (tid < BB) g_fu[tid] = TT;
    const unsigned* w = (const unsigned*)pm;
    int li = 0, lf = 0;
    for (int i = tid; i < 1024; i += 256) {
        unsigned v = w[i];
        li |= (v > 1u);
        lf |= (v != 0u && v != 0x3F800000u);
    }
    int not_int = __syncthreads_or(li);
    int not_flt = __syncthreads_or(lf);
    int cls = (!not_int) ? 0 : ((!not_flt) ? 1 : 2);
    for (int i = tid; i < MR; i += 256) {
        int m;
        if (cls == 0)      m = (((const int*)pm)[i] != 0);
        else if (cls == 1) m = (((const float*)pm)[i] != 0.0f);
        else               m = (((const unsigned char*)pm)[i] != 0);
        out[i] = m;
        if (!m) atomicMin(&g_fu[i >> 10], i & 1023);
    }
}

// ---------------------------------------------------------------------------
// Pack Wq/Wk/Wv (H,C,D) -> transposed (3C, C) fp16
// ---------------------------------------------------------------------------
__global__ void pack_qkv_kernel(const float* __restrict__ Wq,
                                const float* __restrict__ Wk,
                                const float* __restrict__ Wv,
                                __half* __restrict__ oh)
{
    int idx = blockIdx.x * blockDim.x + threadIdx.x;
    if (idx >= 3 * CC * CC) return;
    int j = idx / CC;
    int c = idx % CC;
    const float* W = (j < CC) ? Wq : (j < 2 * CC) ? Wk : Wv;
    int jj = j & (CC - 1);
    int h = jj >> 6, d = jj & 63;
    oh[idx] = __float2half_rn(W[(h * CC + c) * DD + d]);
}

// ---------------------------------------------------------------------------
// Tiled transpose: in (R, Cn) fp32 -> out (Cn, R) fp16
// ---------------------------------------------------------------------------
__global__ void tsplit_kernel(const float* __restrict__ in,
                              __half* __restrict__ oh,
                              int R, int Cn)
{
    __shared__ float t[32][33];
    int c0 = blockIdx.x * 32, r0 = blockIdx.y * 32;
    int x = threadIdx.x, y = threadIdx.y;
#pragma unroll
    for (int i = 0; i < 32; i += 8)
        t[y + i][x] = in[(size_t)(r0 + y + i) * Cn + c0 + x];
    __syncthreads();
#pragma unroll
    for (int i = 0; i < 32; i += 8)
        oh[(size_t)(c0 + y + i) * R + r0 + x] = __float2half_rn(t[x][y + i]);
}

// ---------------------------------------------------------------------------
// LayerNorm + split (fp16 hi/lo)
// ---------------------------------------------------------------------------
__global__ __launch_bounds__(256) void ln_split_kernel(const float* __restrict__ x,
                                                       const float* __restrict__ g,
                                                       const float* __restrict__ b,
                                                       __half* __restrict__ oh,
                                                       __half* __restrict__ ol)
{
    int row = blockIdx.x, tid = threadIdx.x;
    const float* xr = x + (size_t)row * CC;
    float v[4];
    float s = 0.f, ss = 0.f;
#pragma unroll
    for (int i = 0; i < 4; i++) {
        v[i] = xr[tid + i * 256];
        s += v[i];
        ss += v[i] * v[i];
    }
#pragma unroll
    for (int o = 16; o; o >>= 1) {
        s  += __shfl_xor_sync(0xffffffffu, s,  o);
        ss += __shfl_xor_sync(0xffffffffu, ss, o);
    }
    __shared__ float ws[8], wss[8];
    __shared__ float s_m, s_r;
    int wid = tid >> 5;
    if ((tid & 31) == 0) { ws[wid] = s; wss[wid] = ss; }
    __syncthreads();
    if (tid == 0) {
        float S = 0.f, SS = 0.f;
        for (int i = 0; i < 8; i++) { S += ws[i]; SS += wss[i]; }
        float m = S * (1.0f / CC);
        float var = SS * (1.0f / CC) - m * m;
        s_m = m;
        s_r = rsqrtf(var + 1e-5f);
    }
    __syncthreads();
    float m = s_m, r = s_r;
#pragma unroll
    for (int i = 0; i < 4; i++) {
        int c = tid + i * 256;
        float o = (v[i] - m) * r * g[c] + b[c];
        __half hh, ll; split2(o, hh, ll);
        size_t idx = (size_t)row * CC + c;
        oh[idx] = hh; ol[idx] = ll;
    }
}

// ---------------------------------------------------------------------------
// fp16 GEMM (R7 config): D = (Ah[+Al])(M,K) @ Bh^T, B stored (N,K) fp16.
// CTA 128x256, 256 threads / 8 warps (warp tile 64x64), K-chunk 64,
// 3-stage cp.async pipeline. use_al selects the 2-pass corrected path.
// Epilogue: fp32 out, or split hi/lo fp16, or hi-only fp16.
// ---------------------------------------------------------------------------
#define PITCH 72
#define A_TILE_B (128 * PITCH * 2)          // 18432
#define B_TILE_B (256 * PITCH * 2)          // 36864
#define STAGE_B (2 * A_TILE_B + B_TILE_B)   // 73728
#define NSTAGE 3
#define GEMM_SMEM (NSTAGE * STAGE_B)        // 221184

__global__ __launch_bounds__(256, 1) void gemm_mma(
    const __half* __restrict__ Ah, const __half* __restrict__ Al,
    const __half* __restrict__ Bh,
    const float* __restrict__ bias,
    float* __restrict__ outF,
    __half* __restrict__ outH, __half* __restrict__ outL,
    int Ntot, int Ktot, int relu, int use_al)
{
    extern __shared__ __align__(128) char smem[];
    const uint32_t sb0 = smem_u32(smem);
    int tid = threadIdx.x, lane = tid & 31, w = tid >> 5;
    int bm = blockIdx.y * 128, bn = blockIdx.x * 256;
    int wm = (w & 1) * 64, wn = (w >> 1) * 64;
    int nk = Ktot >> 6;

    float acc[4][8][4];
#pragma unroll
    for (int i = 0; i < 4; i++)
#pragma unroll
        for (int j = 0; j < 8; j++)
#pragma unroll
            for (int e = 0; e < 4; e++) acc[i][j][e] = 0.0f;

    auto load_stage = [&](int st, int kc) {
        uint32_t sb = sb0 + st * STAGE_B;
#pragma unroll
        for (int i = 0; i < 16; i++) {
            int idx = tid + i * 256;
            int c = (idx & 7) * 8;
            if (i < 4) {              // Ah
                int r = idx >> 3;
                cp16(sb + (uint32_t)(r * PITCH + c) * 2,
                     Ah + (size_t)(bm + r) * Ktot + kc + c);
            } else if (i < 8) {       // Al (only when used)
                if (use_al) {
                    int r = (idx - 1024) >> 3;
                    cp16(sb + A_TILE_B + (uint32_t)(r * PITCH + c) * 2,
                         Al + (size_t)(bm + r) * Ktot + kc + c);
                }
            } else {                  // Bh
                int r = (idx - 2048) >> 3;
                cp16(sb + 2 * A_TILE_B + (uint32_t)(r * PITCH + c) * 2,
                     Bh + (size_t)(bn + r) * Ktot + kc + c);
            }
        }
    };

    load_stage(0, 0);
    CP_COMMIT();
    if (nk > 1) { load_stage(1, 64); CP_COMMIT(); }

    int lrow = lane & 15;
    int lk = (lane >> 4) * 8;

    for (int kc = 0; kc < nk; kc++) {
        if (kc + 2 < nk) {
            load_stage((kc + 2) % 3, (kc + 2) * 64);
            CP_COMMIT();
            CP_WAIT2();
        } else {
            CP_WAIT0();
        }
        __syncthreads();

        uint32_t sb = sb0 + (kc % 3) * STAGE_B;
#pragma unroll
        for (int ks = 0; ks < 4; ks++) {
            int k0 = ks * 16;
            uint32_t ah[4][4], al[4][4], bh[8][2];
#pragma unroll
            for (int i = 0; i < 4; i++) {
                uint32_t ad = sb + (uint32_t)((wm + i * 16 + lrow) * PITCH + k0 + lk) * 2;
                LDSM4(ah[i], ad);
                if (use_al) LDSM4(al[i], ad + A_TILE_B);
            }
#pragma unroll
            for (int jj = 0; jj < 4; jj++) {
                uint32_t bd = sb + 2 * A_TILE_B +
                              (uint32_t)((wn + jj * 16 + lrow) * PITCH + k0 + lk) * 2;
                uint32_t t[4];
                LDSM4(t, bd);
                bh[jj * 2][0] = t[0]; bh[jj * 2][1] = t[2];
                bh[jj * 2 + 1][0] = t[1]; bh[jj * 2 + 1][1] = t[3];
            }
#pragma unroll
            for (int i = 0; i < 4; i++)
#pragma unroll
                for (int j = 0; j < 8; j++)
                    mma16816(acc[i][j], ah[i], bh[j]);
            if (use_al) {
#pragma unroll
                for (int i = 0; i < 4; i++)
#pragma unroll
                    for (int j = 0; j < 8; j++)
                        mma16816(acc[i][j], al[i], bh[j]);
            }
        }
        __syncthreads();
    }

#pragma unroll
    for (int i = 0; i < 4; i++) {
        int r0 = bm + wm + i * 16 + (lane >> 2);
#pragma unroll
        for (int j = 0; j < 8; j++) {
            int c = bn + wn + j * 8 + (lane & 3) * 2;
            float bx0 = bias ? bias[c] : 0.0f;
            float bx1 = bias ? bias[c + 1] : 0.0f;
#pragma unroll
            for (int hh = 0; hh < 2; hh++) {
                int r = r0 + hh * 8;
                float v0 = acc[i][j][hh * 2 + 0] + bx0;
                float v1 = acc[i][j][hh * 2 + 1] + bx1;
                if (relu) { v0 = fmaxf(v0, 0.0f); v1 = fmaxf(v1, 0.0f); }
                size_t o = (size_t)r * Ntot + c;
                if (outF) {
                    outF[o] = v0;
                    outF[o + 1] = v1;
                } else if (outL) {
                    __half h0, l0, h1, l1;
                    split2(v0, h0, l0);
                    split2(v1, h1, l1);
                    __half2 hp; hp.x = h0; hp.y = h1;
                    __half2 lp; lp.x = l0; lp.y = l1;
                    *(__half2*)(outH + o) = hp;
                    *(__half2*)(outL + o) = lp;
                } else {
                    *(__half2*)(outH + o) = __floats2half2_rn(v0, v1);
                }
            }
        }
    }
}

// ---------------------------------------------------------------------------
// fp16 flash attention: single-pass QK (Qh·Kh — Q-rounding attenuated by the
// 1/32 logit scale, error ~2.5e-5), 2-pass PV (Ph+Pl vs Vh).
// CTA 256 thr (8 warps), q-tile 128, s-tile 64, causal-only sweep,
// double-buffered cp.async over {Kh, Vh, mask}; heavy blocks first.
// ---------------------------------------------------------------------------
#define AT_PITCH 72
#define AQ_TILEB (128 * AT_PITCH * 2)     // 18432
#define AKV_TILEB (64 * AT_PITCH * 2)     // 9216
#define SMASK_OFF (AQ_TILEB + 4 * AKV_TILEB)       // 55296
#define ATT_SMEM (SMASK_OFF + 2 * 64 * 4)          // 55808

__global__ __launch_bounds__(256) void attn_mma(
    const __half* __restrict__ qkvH,
    const __half* __restrict__ qkvL,
    const int* __restrict__ mask,
    __half* __restrict__ outH,
    __half* __restrict__ outL)
{
    extern __shared__ __align__(128) char smem[];
    const uint32_t sb = smem_u32(smem);
    const uint32_t sQh = sb;

    int qi = (int)gridDim.x - 1 - (int)blockIdx.x;   // heavy blocks first
    int bh = blockIdx.y;
    int b = bh >> 4, h = bh & 15;
    int tid = threadIdx.x, lane = tid & 31, w = tid >> 5;
    int wq = w * 16;
    int lrow = lane & 15, lkc = (lane >> 4) * 8;

    const size_t rowbase = (size_t)(b * TT) * (3 * CC) + h * DD;
    const int* gmask = mask + b * TT;
    int* smask = (int*)(smem + SMASK_OFF);

    // Q tile (hi only)
#pragma unroll
    for (int i = 0; i < 4; i++) {
        int idx = tid + i * 256;
        int r = idx >> 3, ch = (idx & 7) * 8;
        uint32_t so = (uint32_t)(r * AT_PITCH + ch) * 2;
        size_t go = rowbase + (size_t)(qi * 128 + r) * (3 * CC) + ch;
        cp16(sQh + so, qkvH + go);
    }

    auto load_stage = [&](int sj) {
        int st = sj & 1;
        uint32_t base = sb + AQ_TILEB + st * (2 * AKV_TILEB);
#pragma unroll
        for (int i = 0; i < 4; i++) {
            int idx = tid + i * 256;
            int tile = idx >> 9;
            int rem = idx & 511;
            int r = rem >> 3, ch = (rem & 7) * 8;
            uint32_t so = base + tile * AKV_TILEB + (uint32_t)(r * AT_PITCH + ch) * 2;
            size_t gk = rowbase + (size_t)(sj * 64 + r) * (3 * CC) + CC + ch;
            if (tile == 0) cp16(so, qkvH + gk);
            else           cp16(so, qkvH + gk + CC);
        }
        if (tid < 16)
            cp16(sb + SMASK_OFF + st * 256 + tid * 16, gmask + sj * 64 + tid * 4);
    };

    int ns = 2 * qi + 2;
    load_stage(0);
    CP_COMMIT();

    float O[8][4];
#pragma unroll
    for (int j = 0; j < 8; j++)
#pragma unroll
        for (int e = 0; e < 4; e++) O[j][e] = 0.0f;
    float lsum0 = 0.0f, lsum1 = 0.0f;

    const float csc = 0.0450842200f;   // log2(e) / 32
    const int t_base = qi * 128 + wq + (lane >> 2);

    for (int sj = 0; sj < ns; sj++) {
        int cur = sj & 1;
        if (sj + 1 < ns) {
            load_stage(sj + 1);
            CP_COMMIT();
            CP_WAIT1();
        } else {
            CP_WAIT0();
        }
        __syncthreads();

        uint32_t kvb = sb + AQ_TILEB + cur * (2 * AKV_TILEB);
        uint32_t sKh = kvb, sVh = kvb + AKV_TILEB;
        const int* mrow = smask + cur * 64;

        // S = Q K^T (single pass)
        float S[8][4];
#pragma unroll
        for (int j = 0; j < 8; j++)
#pragma unroll
            for (int e = 0; e < 4; e++) S[j][e] = 0.0f;

#pragma unroll
        for (int ks = 0; ks < 4; ks++) {
            uint32_t qa[4];
            uint32_t ad = sQh + (uint32_t)((wq + lrow) * AT_PITCH + ks * 16 + lkc) * 2;
            LDSM4(qa, ad);
#pragma unroll
            for (int nj = 0; nj < 4; nj++) {
                uint32_t bd = sKh + (uint32_t)((nj * 16 + lrow) * AT_PITCH + ks * 16 + lkc) * 2;
                uint32_t th[4];
                LDSM4(th, bd);
                uint32_t bh0[2] = {th[0], th[2]}, bh1[2] = {th[1], th[3]};
                mma16816(S[2 * nj],     qa, bh0);
                mma16816(S[2 * nj + 1], qa, bh1);
            }
        }

        // mask + exp2
#pragma unroll
        for (int j = 0; j < 8; j++) {
            int s0 = j * 8 + (lane & 3) * 2;
#pragma unroll
            for (int e = 0; e < 4; e++) {
                int s_l = s0 + (e & 1);
                int s_g = sj * 64 + s_l;
                int t_g = t_base + (e >> 1) * 8;
                float v = S[j][e] * csc;
                if (mrow[s_l] || (s_g > t_g)) v = -1e9f;
                S[j][e] = fex2(v);
            }
            lsum0 += S[j][0] + S[j][1];
            lsum1 += S[j][2] + S[j][3];
        }

        // pack P (hi/lo fp16)
        uint32_t aPh[8][2], aPl[8][2];
#pragma unroll
        for (int j = 0; j < 8; j++) {
            __half2 h0 = __floats2half2_rn(S[j][0], S[j][1]);
            __half2 h1 = __floats2half2_rn(S[j][2], S[j][3]);
            float r00 = S[j][0] - __half2float(h0.x);
            float r01 = S[j][1] - __half2float(h0.y);
            float r10 = S[j][2] - __half2float(h1.x);
            float r11 = S[j][3] - __half2float(h1.y);
            __half2 l0 = __floats2half2_rn(r00, r01);
            __half2 l1 = __floats2half2_rn(r10, r11);
            aPh[j][0] = *(uint32_t*)&h0; aPh[j][1] = *(uint32_t*)&h1;
            aPl[j][0] = *(uint32_t*)&l0; aPl[j][1] = *(uint32_t*)&l1;
        }

        // O += P V (2-pass)
#pragma unroll
        for (int kc = 0; kc < 4; kc++) {
            uint32_t Ahf[4] = {aPh[2 * kc][0], aPh[2 * kc][1],
                               aPh[2 * kc + 1][0], aPh[2 * kc + 1][1]};
            uint32_t Alf[4] = {aPl[2 * kc][0], aPl[2 * kc][1],
                               aPl[2 * kc + 1][0], aPl[2 * kc + 1][1]};
#pragma unroll
            for (int dj = 0; dj < 4; dj++) {
                uint32_t vd = sVh + (uint32_t)((kc * 16 + lrow) * AT_PITCH + dj * 16 + lkc) * 2;
                uint32_t tvh[4];
                LDSM4T(tvh, vd);
                uint32_t bh0[2] = {tvh[0], tvh[1]}, bh1[2] = {tvh[2], tvh[3]};
                mma16816(O[2 * dj],     Ahf, bh0);
                mma16816(O[2 * dj + 1], Ahf, bh1);
                mma16816(O[2 * dj],     Alf, bh0);
                mma16816(O[2 * dj + 1], Alf, bh1);
            }
        }
        __syncthreads();
    }

    // finalize
    lsum0 += __shfl_xor_sync(0xffffffffu, lsum0, 1);
    lsum0 += __shfl_xor_sync(0xffffffffu, lsum0, 2);
    lsum1 += __shfl_xor_sync(0xffffffffu, lsum1, 1);
    lsum1 += __shfl_xor_sync(0xffffffffu, lsum1, 2);
    float inv0 = 1.0f / lsum0;
    float inv1 = 1.0f / lsum1;

#pragma unroll
    for (int hh = 0; hh < 2; hh++) {
        float inv = hh ? inv1 : inv0;
        size_t orow = (size_t)(b * TT + t_base + hh * 8) * CC + h * DD + (lane & 3) * 2;
#pragma unroll
        for (int j = 0; j < 8; j++) {
            float v0 = O[j][hh * 2 + 0] * inv;
            float v1 = O[j][hh * 2 + 1] * inv;
            __half h0, l0, h1, l1;
            split2(v0, h0, l0);
            split2(v1, h1, l1);
            __half2 hp; hp.x = h0; hp.y = h1;
            __half2 lp; lp.x = l0; lp.y = l1;
            *(__half2*)(outH + orow + j * 8) = hp;
            *(__half2*)(outL + orow + j * 8) = lp;
        }
    }
}

// ---------------------------------------------------------------------------
// Fixup: rows t < first_unpadded[b] -> out = mean of V over padded positions.
// ---------------------------------------------------------------------------
__global__ __launch_bounds__(256) void fixup_kernel(
    const __half* __restrict__ qkvH,
    const __half* __restrict__ qkvL,
    const int* __restrict__ mask,
    __half* __restrict__ outH,
    __half* __restrict__ outL)
{
    int b = blockIdx.x;
    int f = g_fu[b];
    if (f == 0) return;
    int tid = threadIdx.x;
    float sum[4] = {0, 0, 0, 0};
    int cnt = 0;
    for (int s = 0; s < TT; s++) {
        if (mask[b * TT + s]) {
            cnt++;
            size_t base = (size_t)(b * TT + s) * (3 * CC) + 2 * CC + tid * 4;
#pragma unroll
            for (int e = 0; e < 4; e++)
                sum[e] += __half2float(qkvH[base + e]) +
                          __half2float(qkvL[base + e]);
        }
    }
    float invc = 1.0f / (float)cnt;
    __half mh[4], ml[4];
#pragma unroll
    for (int e = 0; e < 4; e++) split2(sum[e] * invc, mh[e], ml[e]);
    for (int t = 0; t < f; t++) {
        size_t o = (size_t)(b * TT + t) * CC + tid * 4;
#pragma unroll
        for (int e = 0; e < 4; e++) {
            outH[o + e] = mh[e];
            outL[o + e] = ml[e];
        }
    }
}

// ---------------------------------------------------------------------------
// Launch
// ---------------------------------------------------------------------------
extern "C" void kernel_launch(void* const* d_in, const int* in_sizes, int n_in,
                              void* d_out, int out_size)
{
    const float* x     = (const float*)d_in[0];
    const void*  pmask = d_in[1];
    const float* Wq    = (const float*)d_in[2];
    const float* Wk    = (const float*)d_in[3];
    const float* Wv    = (const float*)d_in[4];
    const float* Wo    = (const float*)d_in[5];
    const float* bo    = (const float*)d_in[6];
    const float* ln1_g = (const float*)d_in[7];
    const float* ln1_b = (const float*)d_in[8];
    const float* ln2_g = (const float*)d_in[9];
    const float* ln2_b = (const float*)d_in[10];
    const float* W1    = (const float*)d_in[11];
    const float* b1    = (const float*)d_in[12];
    const float* W2    = (const float*)d_in[13];
    const float* b2    = (const float*)d_in[14];
    float* out = (float*)d_out;

    void *p_proj, *p_qkvH, *p_qkvL, *p_hH, *p_hL, *p_atH, *p_atL,
         *p_h2H, *p_h2L, *p_f1H, *p_wqH, *p_woH, *p_w1H, *p_w2H, *p_mask;
    cudaGetSymbolAddress(&p_proj, g_proj);
    cudaGetSymbolAddress(&p_qkvH, g_qkvH);
    cudaGetSymbolAddress(&p_qkvL, g_qkvL);
    cudaGetSymbolAddress(&p_hH,   g_hH);
    cudaGetSymbolAddress(&p_hL,   g_hL);
    cudaGetSymbolAddress(&p_atH,  g_atH);
    cudaGetSymbolAddress(&p_atL,  g_atL);
    cudaGetSymbolAddress(&p_h2H,  g_h2H);
    cudaGetSymbolAddress(&p_h2L,  g_h2L);
    cudaGetSymbolAddress(&p_f1H,  g_f1H);
    cudaGetSymbolAddress(&p_wqH,  g_wqH);
    cudaGetSymbolAddress(&p_woH,  g_woH);
    cudaGetSymbolAddress(&p_w1H,  g_w1H);
    cudaGetSymbolAddress(&p_w2H,  g_w2H);
    cudaGetSymbolAddress(&p_mask, g_mask);

    cudaFuncSetAttribute(gemm_mma, cudaFuncAttributeMaxDynamicSharedMemorySize, GEMM_SMEM);
    cudaFuncSetAttribute(attn_mma, cudaFuncAttributeMaxDynamicSharedMemorySize, ATT_SMEM);

    // 1. mask + first-unpadded
    mask_expand_kernel<<<1, 256>>>(pmask, (int*)p_mask);
    // 2. weight prep (fp16)
    pack_qkv_kernel<<<(3 * CC * CC + 255) / 256, 256>>>(Wq, Wk, Wv, (__half*)p_wqH);
    tsplit_kernel<<<dim3(CC / 32, CC / 32), dim3(32, 8)>>>(Wo, (__half*)p_woH, CC, CC);
    tsplit_kernel<<<dim3(FF / 32, CC / 32), dim3(32, 8)>>>(W1, (__half*)p_w1H, CC, FF);
    tsplit_kernel<<<dim3(CC / 32, FF / 32), dim3(32, 8)>>>(W2, (__half*)p_w2H, FF, CC);
    // 3. LN1
    ln_split_kernel<<<MR, 256>>>(x, ln1_g, ln1_b, (__half*)p_hH, (__half*)p_hL);
    // 4. QKV gemm (2-pass, split output for attention/Wo accuracy)
    gemm_mma<<<dim3(3 * CC / 256, MR / 128), 256, GEMM_SMEM>>>(
        (__half*)p_hH, (__half*)p_hL, (__half*)p_wqH, nullptr,
        nullptr, (__half*)p_qkvH, (__half*)p_qkvL, 3 * CC, CC, 0, 1);
    // 5. flash attention + fixup
    attn_mma<<<dim3(TT / 128, BB * HH), 256, ATT_SMEM>>>(
        (const __half*)p_qkvH, (const __half*)p_qkvL, (const int*)p_mask,
        (__half*)p_atH, (__half*)p_atL);
    fixup_kernel<<<BB, 256>>>(
        (const __half*)p_qkvH, (const __half*)p_qkvL, (const int*)p_mask,
        (__half*)p_atH, (__half*)p_atL);
    // 6. Wo projection (2-pass)
    gemm_mma<<<dim3(CC / 256, MR / 128), 256, GEMM_SMEM>>>(
        (__half*)p_atH, (__half*)p_atL, (__half*)p_woH, bo,
        (float*)p_proj, nullptr, nullptr, CC, CC, 0, 1);
    // 7. LN2
    ln_split_kernel<<<MR, 256>>>((const float*)p_proj, ln2_g, ln2_b,
                                 (__half*)p_h2H, (__half*)p_h2L);
    // 8. FFN1 + relu (1-pass, hi-only output)
    gemm_mma<<<dim3(FF / 256, MR / 128), 256, GEMM_SMEM>>>(
        (__half*)p_h2H, nullptr, (__half*)p_w1H, b1,
        nullptr, (__half*)p_f1H, nullptr, FF, CC, 1, 0);
    // 9. FFN2 -> d_out (1-pass)
    gemm_mma<<<dim3(CC / 256, MR / 128), 256, GEMM_SMEM>>>(
        (__half*)p_f1H, nullptr, (__half*)p_w2H, b2,
        out, nullptr, nullptr, CC, FF, 0, 0);
}

// round 11
// speedup vs baseline: 1.8445x; 1.4113x over previous
#include <cuda_runtime.h>
#include <cuda_fp16.h>
#include <cstdint>
#include <math.h>

// Problem dims
#define BB 4
#define TT 1024
#define CC 1024
#define HH 16
#define DD 64
#define FF 4096
#define MR 4096   // B*T

// ---------------------------------------------------------------------------
// Scratch (static device globals)
// ---------------------------------------------------------------------------
__device__ __align__(256) float g_proj[MR * CC];
__device__ __align__(256) __half g_qkv[MR * 3 * CC];
__device__ __align__(256) __half g_h  [MR * CC];
__device__ __align__(256) __half g_at [MR * CC];
__device__ __align__(256) __half g_h2 [MR * CC];
__device__ __align__(256) __half g_f1 [MR * FF];
__device__ __align__(256) __half g_wq [3 * CC * CC];
__device__ __align__(256) __half g_wo [CC * CC];
__device__ __align__(256) __half g_w1 [FF * CC];
__device__ __align__(256) __half g_w2 [CC * FF];
__device__ int g_mask[MR];
__device__ int g_fu[BB];

// ---------------------------------------------------------------------------
// Helpers
// ---------------------------------------------------------------------------
__device__ __forceinline__ uint32_t smem_u32(const void* p) {
    uint32_t a;
    asm("{ .reg .u64 t; cvta.to.shared.u64 t, %1; cvt.u32.u64 %0, t; }" : "=r"(a) : "l"(p));
    return a;
}
__device__ __forceinline__ void cp16(uint32_t s, const void* g) {
    asm volatile("cp.async.cg.shared.global [%0], [%1], 16;" :: "r"(s), "l"(g));
}
#define CP_COMMIT() asm volatile("cp.async.commit_group;" ::: "memory")
#define CP_WAIT2()  asm volatile("cp.async.wait_group 2;"  ::: "memory")
#define CP_WAIT1()  asm volatile("cp.async.wait_group 1;"  ::: "memory")
#define CP_WAIT0()  asm volatile("cp.async.wait_group 0;"  ::: "memory")

#define LDSM4(r, addr) \
    asm volatile("ldmatrix.sync.aligned.m8n8.x4.shared.b16 {%0,%1,%2,%3}, [%4];" \
        : "=r"((r)[0]), "=r"((r)[1]), "=r"((r)[2]), "=r"((r)[3]) : "r"(addr))
#define LDSM4T(r, addr) \
    asm volatile("ldmatrix.sync.aligned.m8n8.x4.trans.shared.b16 {%0,%1,%2,%3}, [%4];" \
        : "=r"((r)[0]), "=r"((r)[1]), "=r"((r)[2]), "=r"((r)[3]) : "r"(addr))

__device__ __forceinline__ void mma16816(float* c, const uint32_t* a, const uint32_t* b) {
    asm volatile("mma.sync.aligned.m16n8k16.row.col.f32.f16.f16.f32 "
        "{%0,%1,%2,%3}, {%4,%5,%6,%7}, {%8,%9}, {%0,%1,%2,%3};"
        : "+f"(c[0]), "+f"(c[1]), "+f"(c[2]), "+f"(c[3])
        : "r"(a[0]), "r"(a[1]), "r"(a[2]), "r"(a[3]), "r"(b[0]), "r"(b[1]));
}

__device__ __forceinline__ float fex2(float x) {
    float r;
    asm("ex2.approx.ftz.f32 %0, %1;" : "=f"(r) : "f"(x));
    return r;
}

// ---------------------------------------------------------------------------
// Mask classify + expand + first-unpadded per batch
// ---------------------------------------------------------------------------
__global__ void mask_expand_kernel(const void* __restrict__ pm, int* __restrict__ out)
{
    int tid = threadIdx.x;
    if (tid < BB) g_fu[tid] = TT;
    const unsigned* w = (const unsigned*)pm;
    int li = 0, lf = 0;
    for (int i = tid; i < 1024; i += 256) {
        unsigned v = w[i];
        li |= (v > 1u);
        lf |= (v != 0u && v != 0x3F800000u);
    }
    int not_int = __syncthreads_or(li);
    int not_flt = __syncthreads_or(lf);
    int cls = (!not_int) ? 0 : ((!not_flt) ? 1 : 2);
    for (int i = tid; i < MR; i += 256) {
        int m;
        if (cls == 0)      m = (((const int*)pm)[i] != 0);
        else if (cls == 1) m = (((const float*)pm)[i] != 0.0f);
        else               m = (((const unsigned char*)pm)[i] != 0);
        out[i] = m;
        if (!m) atomicMin(&g_fu[i >> 10], i & 1023);
    }
}

// ---------------------------------------------------------------------------
// Pack Wq/Wk/Wv (H,C,D) -> transposed (3C, C) fp16
// ---------------------------------------------------------------------------
__global__ void pack_qkv_kernel(const float* __restrict__ Wq,
                                const float* __restrict__ Wk,
                                const float* __restrict__ Wv,
                                __half* __restrict__ oh)
{
    int idx = blockIdx.x * blockDim.x + threadIdx.x;
    if (idx >= 3 * CC * CC) return;
    int j = idx / CC;
    int c = idx % CC;
    const float* W = (j < CC) ? Wq : (j < 2 * CC) ? Wk : Wv;
    int jj = j & (CC - 1);
    int h = jj >> 6, d = jj & 63;
    oh[idx] = __float2half_rn(W[(h * CC + c) * DD + d]);
}

// ---------------------------------------------------------------------------
// Tiled transpose: in (R, Cn) fp32 -> out (Cn, R) fp16
// ---------------------------------------------------------------------------
__global__ void tsplit_kernel(const float* __restrict__ in,
                              __half* __restrict__ oh,
                              int R, int Cn)
{
    __shared__ float t[32][33];
    int c0 = blockIdx.x * 32, r0 = blockIdx.y * 32;
    int x = threadIdx.x, y = threadIdx.y;
#pragma unroll
    for (int i = 0; i < 32; i += 8)
        t[y + i][x] = in[(size_t)(r0 + y + i) * Cn + c0 + x];
    __syncthreads();
#pragma unroll
    for (int i = 0; i < 32; i += 8)
        oh[(size_t)(c0 + y + i) * R + r0 + x] = __float2half_rn(t[x][y + i]);
}

// ---------------------------------------------------------------------------
// LayerNorm -> fp16 (hi only)
// ---------------------------------------------------------------------------
__global__ __launch_bounds__(256) void ln_kernel(const float* __restrict__ x,
                                                 const float* __restrict__ g,
                                                 const float* __restrict__ b,
                                                 __half* __restrict__ oh)
{
    int row = blockIdx.x, tid = threadIdx.x;
    const float* xr = x + (size_t)row * CC;
    float v[4];
    float s = 0.f, ss = 0.f;
#pragma unroll
    for (int i = 0; i < 4; i++) {
        v[i] = xr[tid + i * 256];
        s += v[i];
        ss += v[i] * v[i];
    }
#pragma unroll
    for (int o = 16; o; o >>= 1) {
        s  += __shfl_xor_sync(0xffffffffu, s,  o);
        ss += __shfl_xor_sync(0xffffffffu, ss, o);
    }
    __shared__ float ws[8], wss[8];
    __shared__ float s_m, s_r;
    int wid = tid >> 5;
    if ((tid & 31) == 0) { ws[wid] = s; wss[wid] = ss; }
    __syncthreads();
    if (tid == 0) {
        float S = 0.f, SS = 0.f;
        for (int i = 0; i < 8; i++) { S += ws[i]; SS += wss[i]; }
        float m = S * (1.0f / CC);
        float var = SS * (1.0f / CC) - m * m;
        s_m = m;
        s_r = rsqrtf(var + 1e-5f);
    }
    __syncthreads();
    float m = s_m, r = s_r;
#pragma unroll
    for (int i = 0; i < 4; i++) {
        int c = tid + i * 256;
        float o = (v[i] - m) * r * g[c] + b[c];
        oh[(size_t)row * CC + c] = __float2half_rn(o);
    }
}

// ---------------------------------------------------------------------------
// fp16 1-pass GEMM: D = Ah(M,K) @ Bh^T, B stored (N,K) fp16.
// CTA 128x256, 256 threads / 8 warps (warp tile 64x64), K-chunk 64,
// 3-stage cp.async pipeline.
// ---------------------------------------------------------------------------
#define PITCH 72
#define A_TILE_B (128 * PITCH * 2)          // 18432
#define B_TILE_B (256 * PITCH * 2)          // 36864
#define STAGE_B (A_TILE_B + B_TILE_B)       // 55296
#define NSTAGE 3
#define GEMM_SMEM (NSTAGE * STAGE_B)        // 165888

__global__ __launch_bounds__(256, 1) void gemm_mma(
    const __half* __restrict__ Ah,
    const __half* __restrict__ Bh,
    const float* __restrict__ bias,
    float* __restrict__ outF,
    __half* __restrict__ outH,
    int Ntot, int Ktot, int relu)
{
    extern __shared__ __align__(128) char smem[];
    const uint32_t sb0 = smem_u32(smem);
    int tid = threadIdx.x, lane = tid & 31, w = tid >> 5;
    int bm = blockIdx.y * 128, bn = blockIdx.x * 256;
    int wm = (w & 1) * 64, wn = (w >> 1) * 64;
    int nk = Ktot >> 6;

    float acc[4][8][4];
#pragma unroll
    for (int i = 0; i < 4; i++)
#pragma unroll
        for (int j = 0; j < 8; j++)
#pragma unroll
            for (int e = 0; e < 4; e++) acc[i][j][e] = 0.0f;

    auto load_stage = [&](int st, int kc) {
        uint32_t sb = sb0 + st * STAGE_B;
#pragma unroll
        for (int i = 0; i < 12; i++) {
            int idx = tid + i * 256;          // 0..3071
            int c = (idx & 7) * 8;
            if (idx < 1024) {                 // Ah: 128 rows x 64 cols
                int r = idx >> 3;
                cp16(sb + (uint32_t)(r * PITCH + c) * 2,
                     Ah + (size_t)(bm + r) * Ktot + kc + c);
            } else {                          // Bh: 256 rows x 64 cols
                int r = (idx - 1024) >> 3;
                cp16(sb + A_TILE_B + (uint32_t)(r * PITCH + c) * 2,
                     Bh + (size_t)(bn + r) * Ktot + kc + c);
            }
        }
    };

    load_stage(0, 0);
    CP_COMMIT();
    if (nk > 1) { load_stage(1, 64); CP_COMMIT(); }

    int lrow = lane & 15;
    int lk = (lane >> 4) * 8;

    for (int kc = 0; kc < nk; kc++) {
        if (kc + 2 < nk) {
            load_stage((kc + 2) % 3, (kc + 2) * 64);
            CP_COMMIT();
            CP_WAIT2();
        } else {
            CP_WAIT0();
        }
        __syncthreads();

        uint32_t sb = sb0 + (kc % 3) * STAGE_B;
#pragma unroll
        for (int ks = 0; ks < 4; ks++) {
            int k0 = ks * 16;
            uint32_t ah[4][4], bh[8][2];
#pragma unroll
            for (int i = 0; i < 4; i++) {
                uint32_t ad = sb + (uint32_t)((wm + i * 16 + lrow) * PITCH + k0 + lk) * 2;
                LDSM4(ah[i], ad);
            }
#pragma unroll
            for (int jj = 0; jj < 4; jj++) {
                uint32_t bd = sb + A_TILE_B +
                              (uint32_t)((wn + jj * 16 + lrow) * PITCH + k0 + lk) * 2;
                uint32_t t[4];
                LDSM4(t, bd);
                bh[jj * 2][0] = t[0]; bh[jj * 2][1] = t[2];
                bh[jj * 2 + 1][0] = t[1]; bh[jj * 2 + 1][1] = t[3];
            }
#pragma unroll
            for (int i = 0; i < 4; i++)
#pragma unroll
                for (int j = 0; j < 8; j++)
                    mma16816(acc[i][j], ah[i], bh[j]);
        }
        __syncthreads();
    }

#pragma unroll
    for (int i = 0; i < 4; i++) {
        int r0 = bm + wm + i * 16 + (lane >> 2);
#pragma unroll
        for (int j = 0; j < 8; j++) {
            int c = bn + wn + j * 8 + (lane & 3) * 2;
            float bx0 = bias ? bias[c] : 0.0f;
            float bx1 = bias ? bias[c + 1] : 0.0f;
#pragma unroll
            for (int hh = 0; hh < 2; hh++) {
                int r = r0 + hh * 8;
                float v0 = acc[i][j][hh * 2 + 0] + bx0;
                float v1 = acc[i][j][hh * 2 + 1] + bx1;
                if (relu) { v0 = fmaxf(v0, 0.0f); v1 = fmaxf(v1, 0.0f); }
                size_t o = (size_t)r * Ntot + c;
                if (outF) {
                    outF[o] = v0;
                    outF[o + 1] = v1;
                } else {
                    *(__half2*)(outH + o) = __floats2half2_rn(v0, v1);
                }
            }
        }
    }
}

// ---------------------------------------------------------------------------
// fp16 flash attention: single-pass QK, 2-pass PV (Ph+Pl vs Vh).
// CTA 256 thr (8 warps), q-tile 128, s-tile 64, causal-only sweep,
// double-buffered cp.async over {Kh, Vh, mask}; heavy blocks first.
// Output: hi-only fp16.
// ---------------------------------------------------------------------------
#define AT_PITCH 72
#define AQ_TILEB (128 * AT_PITCH * 2)     // 18432
#define AKV_TILEB (64 * AT_PITCH * 2)     // 9216
#define SMASK_OFF (AQ_TILEB + 4 * AKV_TILEB)       // 55296
#define ATT_SMEM (SMASK_OFF + 2 * 64 * 4)          // 55808

__global__ __launch_bounds__(256) void attn_mma(
    const __half* __restrict__ qkv,
    const int* __restrict__ mask,
    __half* __restrict__ outp)
{
    extern __shared__ __align__(128) char smem[];
    const uint32_t sb = smem_u32(smem);
    const uint32_t sQ = sb;

    int qi = (int)gridDim.x - 1 - (int)blockIdx.x;   // heavy blocks first
    int bh = blockIdx.y;
    int b = bh >> 4, h = bh & 15;
    int tid = threadIdx.x, lane = tid & 31, w = tid >> 5;
    int wq = w * 16;
    int lrow = lane & 15, lkc = (lane >> 4) * 8;

    const size_t rowbase = (size_t)(b * TT) * (3 * CC) + h * DD;
    const int* gmask = mask + b * TT;
    int* smask = (int*)(smem + SMASK_OFF);

    // Q tile
#pragma unroll
    for (int i = 0; i < 4; i++) {
        int idx = tid + i * 256;
        int r = idx >> 3, ch = (idx & 7) * 8;
        uint32_t so = (uint32_t)(r * AT_PITCH + ch) * 2;
        size_t go = rowbase + (size_t)(qi * 128 + r) * (3 * CC) + ch;
        cp16(sQ + so, qkv + go);
    }

    auto load_stage = [&](int sj) {
        int st = sj & 1;
        uint32_t base = sb + AQ_TILEB + st * (2 * AKV_TILEB);
#pragma unroll
        for (int i = 0; i < 4; i++) {
            int idx = tid + i * 256;
            int tile = idx >> 9;
            int rem = idx & 511;
            int r = rem >> 3, ch = (rem & 7) * 8;
            uint32_t so = base + tile * AKV_TILEB + (uint32_t)(r * AT_PITCH + ch) * 2;
            size_t gk = rowbase + (size_t)(sj * 64 + r) * (3 * CC) + CC + ch;
            if (tile == 0) cp16(so, qkv + gk);
            else           cp16(so, qkv + gk + CC);
        }
        if (tid < 16)
            cp16(sb + SMASK_OFF + st * 256 + tid * 16, gmask + sj * 64 + tid * 4);
    };

    int ns = 2 * qi + 2;
    load_stage(0);
    CP_COMMIT();

    float O[8][4];
#pragma unroll
    for (int j = 0; j < 8; j++)
#pragma unroll
        for (int e = 0; e < 4; e++) O[j][e] = 0.0f;
    float lsum0 = 0.0f, lsum1 = 0.0f;

    const float csc = 0.0450842200f;   // log2(e) / 32
    const int t_base = qi * 128 + wq + (lane >> 2);

    for (int sj = 0; sj < ns; sj++) {
        int cur = sj & 1;
        if (sj + 1 < ns) {
            load_stage(sj + 1);
            CP_COMMIT();
            CP_WAIT1();
        } else {
            CP_WAIT0();
        }
        __syncthreads();

        uint32_t kvb = sb + AQ_TILEB + cur * (2 * AKV_TILEB);
        uint32_t sK = kvb, sV = kvb + AKV_TILEB;
        const int* mrow = smask + cur * 64;

        // S = Q K^T (single pass)
        float S[8][4];
#pragma unroll
        for (int j = 0; j < 8; j++)
#pragma unroll
            for (int e = 0; e < 4; e++) S[j][e] = 0.0f;

#pragma unroll
        for (int ks = 0; ks < 4; ks++) {
            uint32_t qa[4];
            uint32_t ad = sQ + (uint32_t)((wq + lrow) * AT_PITCH + ks * 16 + lkc) * 2;
            LDSM4(qa, ad);
#pragma unroll
            for (int nj = 0; nj < 4; nj++) {
                uint32_t bd = sK + (uint32_t)((nj * 16 + lrow) * AT_PITCH + ks * 16 + lkc) * 2;
                uint32_t th[4];
                LDSM4(th, bd);
                uint32_t bh0[2] = {th[0], th[2]}, bh1[2] = {th[1], th[3]};
                mma16816(S[2 * nj],     qa, bh0);
                mma16816(S[2 * nj + 1], qa, bh1);
            }
        }

        // mask + exp2
#pragma unroll
        for (int j = 0; j < 8; j++) {
            int s0 = j * 8 + (lane & 3) * 2;
#pragma unroll
            for (int e = 0; e < 4; e++) {
                int s_l = s0 + (e & 1);
                int s_g = sj * 64 + s_l;
                int t_g = t_base + (e >> 1) * 8;
                float v = S[j][e] * csc;
                if (mrow[s_l] || (s_g > t_g)) v = -1e9f;
                S[j][e] = fex2(v);
            }
            lsum0 += S[j][0] + S[j][1];
            lsum1 += S[j][2] + S[j][3];
        }

        // pack P (hi/lo fp16)
        uint32_t aPh[8][2], aPl[8][2];
#pragma unroll
        for (int j = 0; j < 8; j++) {
            __half2 h0 = __floats2half2_rn(S[j][0], S[j][1]);
            __half2 h1 = __floats2half2_rn(S[j][2], S[j][3]);
            float r00 = S[j][0] - __half2float(h0.x);
            float r01 = S[j][1] - __half2float(h0.y);
            float r10 = S[j][2] - __half2float(h1.x);
            float r11 = S[j][3] - __half2float(h1.y);
            __half2 l0 = __floats2half2_rn(r00, r01);
            __half2 l1 = __floats2half2_rn(r10, r11);
            aPh[j][0] = *(uint32_t*)&h0; aPh[j][1] = *(uint32_t*)&h1;
            aPl[j][0] = *(uint32_t*)&l0; aPl[j][1] = *(uint32_t*)&l1;
        }

        // O += P V (2-pass)
#pragma unroll
        for (int kc = 0; kc < 4; kc++) {
            uint32_t Ahf[4] = {aPh[2 * kc][0], aPh[2 * kc][1],
                               aPh[2 * kc + 1][0], aPh[2 * kc + 1][1]};
            uint32_t Alf[4] = {aPl[2 * kc][0], aPl[2 * kc][1],
                               aPl[2 * kc + 1][0], aPl[2 * kc + 1][1]};
#pragma unroll
            for (int dj = 0; dj < 4; dj++) {
                uint32_t vd = sV + (uint32_t)((kc * 16 + lrow) * AT_PITCH + dj * 16 + lkc) * 2;
                uint32_t tvh[4];
                LDSM4T(tvh, vd);
                uint32_t bh0[2] = {tvh[0], tvh[1]}, bh1[2] = {tvh[2], tvh[3]};
                mma16816(O[2 * dj],     Ahf, bh0);
                mma16816(O[2 * dj + 1], Ahf, bh1);
                mma16816(O[2 * dj],     Alf, bh0);
                mma16816(O[2 * dj + 1], Alf, bh1);
            }
        }
        __syncthreads();
    }

    // finalize (hi-only output)
    lsum0 += __shfl_xor_sync(0xffffffffu, lsum0, 1);
    lsum0 += __shfl_xor_sync(0xffffffffu, lsum0, 2);
    lsum1 += __shfl_xor_sync(0xffffffffu, lsum1, 1);
    lsum1 += __shfl_xor_sync(0xffffffffu, lsum1, 2);
    float inv0 = 1.0f / lsum0;
    float inv1 = 1.0f / lsum1;

#pragma unroll
    for (int hh = 0; hh < 2; hh++) {
        float inv = hh ? inv1 : inv0;
        size_t orow = (size_t)(b * TT + t_base + hh * 8) * CC + h * DD + (lane & 3) * 2;
#pragma unroll
        for (int j = 0; j < 8; j++) {
            float v0 = O[j][hh * 2 + 0] * inv;
            float v1 = O[j][hh * 2 + 1] * inv;
            *(__half2*)(outp + orow + j * 8) = __floats2half2_rn(v0, v1);
        }
    }
}

// ---------------------------------------------------------------------------
// Fixup: rows t < first_unpadded[b] -> out = mean of V over padded positions.
// ---------------------------------------------------------------------------
__global__ __launch_bounds__(256) void fixup_kernel(
    const __half* __restrict__ qkv,
    const int* __restrict__ mask,
    __half* __restrict__ outp)
{
    int b = blockIdx.x;
    int f = g_fu[b];
    if (f == 0) return;
    int tid = threadIdx.x;
    float sum[4] = {0, 0, 0, 0};
    int cnt = 0;
    for (int s = 0; s < TT; s++) {
        if (mask[b * TT + s]) {
            cnt++;
            size_t base = (size_t)(b * TT + s) * (3 * CC) + 2 * CC + tid * 4;
#pragma unroll
            for (int e = 0; e < 4; e++)
                sum[e] += __half2float(qkv[base + e]);
        }
    }
    float invc = 1.0f / (float)cnt;
    __half mh[4];
#pragma unroll
    for (int e = 0; e < 4; e++) mh[e] = __float2half_rn(sum[e] * invc);
    for (int t = 0; t < f; t++) {
        size_t o = (size_t)(b * TT + t) * CC + tid * 4;
#pragma unroll
        for (int e = 0; e < 4; e++)
            outp[o + e] = mh[e];
    }
}

// ---------------------------------------------------------------------------
// Launch
// ---------------------------------------------------------------------------
extern "C" void kernel_launch(void* const* d_in, const int* in_sizes, int n_in,
                              void* d_out, int out_size)
{
    const float* x     = (const float*)d_in[0];
    const void*  pmask = d_in[1];
    const float* Wq    = (const float*)d_in[2];
    const float* Wk    = (const float*)d_in[3];
    const float* Wv    = (const float*)d_in[4];
    const float* Wo    = (const float*)d_in[5];
    const float* bo    = (const float*)d_in[6];
    const float* ln1_g = (const float*)d_in[7];
    const float* ln1_b = (const float*)d_in[8];
    const float* ln2_g = (const float*)d_in[9];
    const float* ln2_b = (const float*)d_in[10];
    const float* W1    = (const float*)d_in[11];
    const float* b1    = (const float*)d_in[12];
    const float* W2    = (const float*)d_in[13];
    const float* b2    = (const float*)d_in[14];
    float* out = (float*)d_out;

    void *p_proj, *p_qkv, *p_h, *p_at, *p_h2, *p_f1,
         *p_wq, *p_wo, *p_w1, *p_w2, *p_mask;
    cudaGetSymbolAddress(&p_proj, g_proj);
    cudaGetSymbolAddress(&p_qkv,  g_qkv);
    cudaGetSymbolAddress(&p_h,    g_h);
    cudaGetSymbolAddress(&p_at,   g_at);
    cudaGetSymbolAddress(&p_h2,   g_h2);
    cudaGetSymbolAddress(&p_f1,   g_f1);
    cudaGetSymbolAddress(&p_wq,   g_wq);
    cudaGetSymbolAddress(&p_wo,   g_wo);
    cudaGetSymbolAddress(&p_w1,   g_w1);
    cudaGetSymbolAddress(&p_w2,   g_w2);
    cudaGetSymbolAddress(&p_mask, g_mask);

    cudaFuncSetAttribute(gemm_mma, cudaFuncAttributeMaxDynamicSharedMemorySize, GEMM_SMEM);
    cudaFuncSetAttribute(attn_mma, cudaFuncAttributeMaxDynamicSharedMemorySize, ATT_SMEM);

    // 1. mask + first-unpadded
    mask_expand_kernel<<<1, 256>>>(pmask, (int*)p_mask);
    // 2. weight prep (fp16)
    pack_qkv_kernel<<<(3 * CC * CC + 255) / 256, 256>>>(Wq, Wk, Wv, (__half*)p_wq);
    tsplit_kernel<<<dim3(CC / 32, CC / 32), dim3(32, 8)>>>(Wo, (__half*)p_wo, CC, CC);
    tsplit_kernel<<<dim3(FF / 32, CC / 32), dim3(32, 8)>>>(W1, (__half*)p_w1, CC, FF);
    tsplit_kernel<<<dim3(CC / 32, FF / 32), dim3(32, 8)>>>(W2, (__half*)p_w2, FF, CC);
    // 3. LN1 (hi only)
    ln_kernel<<<MR, 256>>>(x, ln1_g, ln1_b, (__half*)p_h);
    // 4. QKV gemm (1-pass)
    gemm_mma<<<dim3(3 * CC / 256, MR / 128), 256, GEMM_SMEM>>>(
        (__half*)p_h, (__half*)p_wq, nullptr,
        nullptr, (__half*)p_qkv, 3 * CC, CC, 0);
    // 5. flash attention + fixup
    attn_mma<<<dim3(TT / 128, BB * HH), 256, ATT_SMEM>>>(
        (const __half*)p_qkv, (const int*)p_mask, (__half*)p_at);
    fixup_kernel<<<BB, 256>>>(
        (const __half*)p_qkv, (const int*)p_mask, (__half*)p_at);
    // 6. Wo projection (1-pass) -> fp32 proj
    gemm_mma<<<dim3(CC / 256, MR / 128), 256, GEMM_SMEM>>>(
        (__half*)p_at, (__half*)p_wo, bo,
        (float*)p_proj, nullptr, CC, CC, 0);
    // 7. LN2 (hi only)
    ln_kernel<<<MR, 256>>>((const float*)p_proj, ln2_g, ln2_b, (__half*)p_h2);
    // 8. FFN1 + relu (1-pass)
    gemm_mma<<<dim3(FF / 256, MR / 128), 256, GEMM_SMEM>>>(
        (__half*)p_h2, (__half*)p_w1, b1,
        nullptr, (__half*)p_f1, FF, CC, 1);
    // 9. FFN2 -> d_out (1-pass)
    gemm_mma<<<dim3(CC / 256, MR / 128), 256, GEMM_SMEM>>>(
        (__half*)p_f1, (__half*)p_w2, b2,
        out, nullptr, CC, FF, 0);
}

// round 13
// speedup vs baseline: 1.8883x; 1.0237x over previous
#include <cuda_runtime.h>
#include <cuda_fp16.h>
#include <cstdint>
#include <math.h>

// Problem dims
#define BB 4
#define TT 1024
#define CC 1024
#define HH 16
#define DD 64
#define FF 4096
#define MR 4096   // B*T

// ---------------------------------------------------------------------------
// Scratch (static device globals)
// ---------------------------------------------------------------------------
__device__ __align__(256) float g_proj[MR * CC];
__device__ __align__(256) __half g_qkv[MR * 3 * CC];
__device__ __align__(256) __half g_h  [MR * CC];
__device__ __align__(256) __half g_at [MR * CC];
__device__ __align__(256) __half g_h2 [MR * CC];
__device__ __align__(256) __half g_f1 [MR * FF];
__device__ __align__(256) __half g_wq [3 * CC * CC];
__device__ __align__(256) __half g_wo [CC * CC];
__device__ __align__(256) __half g_w1 [FF * CC];
__device__ __align__(256) __half g_w2 [CC * FF];
__device__ int g_mask[MR];
__device__ int g_fu[BB];

// ---------------------------------------------------------------------------
// Helpers
// ---------------------------------------------------------------------------
__device__ __forceinline__ uint32_t smem_u32(const void* p) {
    uint32_t a;
    asm("{ .reg .u64 t; cvta.to.shared.u64 t, %1; cvt.u32.u64 %0, t; }" : "=r"(a) : "l"(p));
    return a;
}
__device__ __forceinline__ void cp16(uint32_t s, const void* g) {
    asm volatile("cp.async.cg.shared.global [%0], [%1], 16;" :: "r"(s), "l"(g));
}
#define CP_COMMIT() asm volatile("cp.async.commit_group;" ::: "memory")
#define CP_WAIT2()  asm volatile("cp.async.wait_group 2;"  ::: "memory")
#define CP_WAIT1()  asm volatile("cp.async.wait_group 1;"  ::: "memory")
#define CP_WAIT0()  asm volatile("cp.async.wait_group 0;"  ::: "memory")

#define LDSM4(r, addr) \
    asm volatile("ldmatrix.sync.aligned.m8n8.x4.shared.b16 {%0,%1,%2,%3}, [%4];" \
        : "=r"((r)[0]), "=r"((r)[1]), "=r"((r)[2]), "=r"((r)[3]) : "r"(addr))
#define LDSM4T(r, addr) \
    asm volatile("ldmatrix.sync.aligned.m8n8.x4.trans.shared.b16 {%0,%1,%2,%3}, [%4];" \
        : "=r"((r)[0]), "=r"((r)[1]), "=r"((r)[2]), "=r"((r)[3]) : "r"(addr))

__device__ __forceinline__ void mma16816(float* c, const uint32_t* a, const uint32_t* b) {
    asm volatile("mma.sync.aligned.m16n8k16.row.col.f32.f16.f16.f32 "
        "{%0,%1,%2,%3}, {%4,%5,%6,%7}, {%8,%9}, {%0,%1,%2,%3};"
        : "+f"(c[0]), "+f"(c[1]), "+f"(c[2]), "+f"(c[3])
        : "r"(a[0]), "r"(a[1]), "r"(a[2]), "r"(a[3]), "r"(b[0]), "r"(b[1]));
}

__device__ __forceinline__ float fex2(float x) {
    float r;
    asm("ex2.approx.ftz.f32 %0, %1;" : "=f"(r) : "f"(x));
    return r;
}

// ---------------------------------------------------------------------------
// Mask classify + expand + first-unpadded per batch
// ---------------------------------------------------------------------------
__global__ void mask_expand_kernel(const void* __restrict__ pm, int* __restrict__ out)
{
    int tid = threadIdx.x;
    if (tid < BB) g_fu[tid] = TT;
    const unsigned* w = (const unsigned*)pm;
    int li = 0, lf = 0;
    for (int i = tid; i < 1024; i += 256) {
        unsigned v = w[i];
        li |= (v > 1u);
        lf |= (v != 0u && v != 0x3F800000u);
    }
    int not_int = __syncthreads_or(li);
    int not_flt = __syncthreads_or(lf);
    int cls = (!not_int) ? 0 : ((!not_flt) ? 1 : 2);
    for (int i = tid; i < MR; i += 256) {
        int m;
        if (cls == 0)      m = (((const int*)pm)[i] != 0);
        else if (cls == 1) m = (((const float*)pm)[i] != 0.0f);
        else               m = (((const unsigned char*)pm)[i] != 0);
        out[i] = m;
        if (!m) atomicMin(&g_fu[i >> 10], i & 1023);
    }
}

// ---------------------------------------------------------------------------
// Pack Wq/Wk/Wv (H,C,D) -> transposed (3C, C) fp16
// ---------------------------------------------------------------------------
__global__ void pack_qkv_kernel(const float* __restrict__ Wq,
                                const float* __restrict__ Wk,
                                const float* __restrict__ Wv,
                                __half* __restrict__ oh)
{
    int idx = blockIdx.x * blockDim.x + threadIdx.x;
    if (idx >= 3 * CC * CC) return;
    int j = idx / CC;
    int c = idx % CC;
    const float* W = (j < CC) ? Wq : (j < 2 * CC) ? Wk : Wv;
    int jj = j & (CC - 1);
    int h = jj >> 6, d = jj & 63;
    oh[idx] = __float2half_rn(W[(h * CC + c) * DD + d]);
}

// ---------------------------------------------------------------------------
// Tiled transpose: in (R, Cn) fp32 -> out (Cn, R) fp16
// ---------------------------------------------------------------------------
__global__ void tsplit_kernel(const float* __restrict__ in,
                              __half* __restrict__ oh,
                              int R, int Cn)
{
    __shared__ float t[32][33];
    int c0 = blockIdx.x * 32, r0 = blockIdx.y * 32;
    int x = threadIdx.x, y = threadIdx.y;
#pragma unroll
    for (int i = 0; i < 32; i += 8)
        t[y + i][x] = in[(size_t)(r0 + y + i) * Cn + c0 + x];
    __syncthreads();
#pragma unroll
    for (int i = 0; i < 32; i += 8)
        oh[(size_t)(c0 + y + i) * R + r0 + x] = __float2half_rn(t[x][y + i]);
}

// ---------------------------------------------------------------------------
// LayerNorm -> fp16 (hi only)
// ---------------------------------------------------------------------------
__global__ __launch_bounds__(256) void ln_kernel(const float* __restrict__ x,
                                                 const float* __restrict__ g,
                                                 const float* __restrict__ b,
                                                 __half* __restrict__ oh)
{
    int row = blockIdx.x, tid = threadIdx.x;
    const float* xr = x + (size_t)row * CC;
    float v[4];
    float s = 0.f, ss = 0.f;
#pragma unroll
    for (int i = 0; i < 4; i++) {
        v[i] = xr[tid + i * 256];
        s += v[i];
        ss += v[i] * v[i];
    }
#pragma unroll
    for (int o = 16; o; o >>= 1) {
        s  += __shfl_xor_sync(0xffffffffu, s,  o);
        ss += __shfl_xor_sync(0xffffffffu, ss, o);
    }
    __shared__ float ws[8], wss[8];
    __shared__ float s_m, s_r;
    int wid = tid >> 5;
    if ((tid & 31) == 0) { ws[wid] = s; wss[wid] = ss; }
    __syncthreads();
    if (tid == 0) {
        float S = 0.f, SS = 0.f;
        for (int i = 0; i < 8; i++) { S += ws[i]; SS += wss[i]; }
        float m = S * (1.0f / CC);
        float var = SS * (1.0f / CC) - m * m;
        s_m = m;
        s_r = rsqrtf(var + 1e-5f);
    }
    __syncthreads();
    float m = s_m, r = s_r;
#pragma unroll
    for (int i = 0; i < 4; i++) {
        int c = tid + i * 256;
        float o = (v[i] - m) * r * g[c] + b[c];
        oh[(size_t)row * CC + c] = __float2half_rn(o);
    }
}

// ---------------------------------------------------------------------------
// fp16 1-pass GEMM: D = Ah(M,K) @ Bh^T, B stored (N,K) fp16.
// CTA 128x256, 256 threads / 8 warps (warp tile 64x64), K-chunk 64,
// 3-stage cp.async pipeline.
// ---------------------------------------------------------------------------
#define PITCH 72
#define A_TILE_B (128 * PITCH * 2)          // 18432
#define B_TILE_B (256 * PITCH * 2)          // 36864
#define STAGE_B (A_TILE_B + B_TILE_B)       // 55296
#define NSTAGE 3
#define GEMM_SMEM (NSTAGE * STAGE_B)        // 165888

__global__ __launch_bounds__(256, 1) void gemm_mma(
    const __half* __restrict__ Ah,
    const __half* __restrict__ Bh,
    const float* __restrict__ bias,
    float* __restrict__ outF,
    __half* __restrict__ outH,
    int Ntot, int Ktot, int relu)
{
    extern __shared__ __align__(128) char smem[];
    const uint32_t sb0 = smem_u32(smem);
    int tid = threadIdx.x, lane = tid & 31, w = tid >> 5;
    int bm = blockIdx.y * 128, bn = blockIdx.x * 256;
    int wm = (w & 1) * 64, wn = (w >> 1) * 64;
    int nk = Ktot >> 6;

    float acc[4][8][4];
#pragma unroll
    for (int i = 0; i < 4; i++)
#pragma unroll
        for (int j = 0; j < 8; j++)
#pragma unroll
            for (int e = 0; e < 4; e++) acc[i][j][e] = 0.0f;

    auto load_stage = [&](int st, int kc) {
        uint32_t sb = sb0 + st * STAGE_B;
#pragma unroll
        for (int i = 0; i < 12; i++) {
            int idx = tid + i * 256;          // 0..3071
            int c = (idx & 7) * 8;
            if (idx < 1024) {                 // Ah: 128 rows x 64 cols
                int r = idx >> 3;
                cp16(sb + (uint32_t)(r * PITCH + c) * 2,
                     Ah + (size_t)(bm + r) * Ktot + kc + c);
            } else {                          // Bh: 256 rows x 64 cols
                int r = (idx - 1024) >> 3;
                cp16(sb + A_TILE_B + (uint32_t)(r * PITCH + c) * 2,
                     Bh + (size_t)(bn + r) * Ktot + kc + c);
            }
        }
    };

    load_stage(0, 0);
    CP_COMMIT();
    if (nk > 1) { load_stage(1, 64); CP_COMMIT(); }

    int lrow = lane & 15;
    int lk = (lane >> 4) * 8;

    for (int kc = 0; kc < nk; kc++) {
        if (kc + 2 < nk) {
            load_stage((kc + 2) % 3, (kc + 2) * 64);
            CP_COMMIT();
            CP_WAIT2();
        } else {
            CP_WAIT0();
        }
        __syncthreads();

        uint32_t sb = sb0 + (kc % 3) * STAGE_B;
#pragma unroll
        for (int ks = 0; ks < 4; ks++) {
            int k0 = ks * 16;
            uint32_t ah[4][4], bh[8][2];
#pragma unroll
            for (int i = 0; i < 4; i++) {
                uint32_t ad = sb + (uint32_t)((wm + i * 16 + lrow) * PITCH + k0 + lk) * 2;
                LDSM4(ah[i], ad);
            }
#pragma unroll
            for (int jj = 0; jj < 4; jj++) {
                uint32_t bd = sb + A_TILE_B +
                              (uint32_t)((wn + jj * 16 + lrow) * PITCH + k0 + lk) * 2;
                uint32_t t[4];
                LDSM4(t, bd);
                bh[jj * 2][0] = t[0]; bh[jj * 2][1] = t[2];
                bh[jj * 2 + 1][0] = t[1]; bh[jj * 2 + 1][1] = t[3];
            }
#pragma unroll
            for (int i = 0; i < 4; i++)
#pragma unroll
                for (int j = 0; j < 8; j++)
                    mma16816(acc[i][j], ah[i], bh[j]);
        }
        __syncthreads();
    }

#pragma unroll
    for (int i = 0; i < 4; i++) {
        int r0 = bm + wm + i * 16 + (lane >> 2);
#pragma unroll
        for (int j = 0; j < 8; j++) {
            int c = bn + wn + j * 8 + (lane & 3) * 2;
            float bx0 = bias ? bias[c] : 0.0f;
            float bx1 = bias ? bias[c + 1] : 0.0f;
#pragma unroll
            for (int hh = 0; hh < 2; hh++) {
                int r = r0 + hh * 8;
                float v0 = acc[i][j][hh * 2 + 0] + bx0;
                float v1 = acc[i][j][hh * 2 + 1] + bx1;
                if (relu) { v0 = fmaxf(v0, 0.0f); v1 = fmaxf(v1, 0.0f); }
                size_t o = (size_t)r * Ntot + c;
                if (outF) {
                    outF[o] = v0;
                    outF[o + 1] = v1;
                } else {
                    *(__half2*)(outH + o) = __floats2half2_rn(v0, v1);
                }
            }
        }
    }
}

// ---------------------------------------------------------------------------
// fp16 flash attention: single-pass QK, single-pass PV.
// CTA 256 thr (8 warps), q-tile 128, s-tile 64, causal-only sweep,
// double-buffered cp.async over {Kh, Vh, mask}; heavy blocks first.
// ---------------------------------------------------------------------------
#define AT_PITCH 72
#define AQ_TILEB (128 * AT_PITCH * 2)     // 18432
#define AKV_TILEB (64 * AT_PITCH * 2)     // 9216
#define SMASK_OFF (AQ_TILEB + 4 * AKV_TILEB)       // 55296
#define ATT_SMEM (SMASK_OFF + 2 * 64 * 4)          // 55808

__global__ __launch_bounds__(256) void attn_mma(
    const __half* __restrict__ qkv,
    const int* __restrict__ mask,
    __half* __restrict__ outp)
{
    extern __shared__ __align__(128) char smem[];
    const uint32_t sb = smem_u32(smem);
    const uint32_t sQ = sb;

    int qi = (int)gridDim.x - 1 - (int)blockIdx.x;   // heavy blocks first
    int bh = blockIdx.y;
    int b = bh >> 4, h = bh & 15;
    int tid = threadIdx.x, lane = tid & 31, w = tid >> 5;
    int wq = w * 16;
    int lrow = lane & 15, lkc = (lane >> 4) * 8;

    const size_t rowbase = (size_t)(b * TT) * (3 * CC) + h * DD;
    const int* gmask = mask + b * TT;
    int* smask = (int*)(smem + SMASK_OFF);

    // Q tile
#pragma unroll
    for (int i = 0; i < 4; i++) {
        int idx = tid + i * 256;
        int r = idx >> 3, ch = (idx & 7) * 8;
        uint32_t so = (uint32_t)(r * AT_PITCH + ch) * 2;
        size_t go = rowbase + (size_t)(qi * 128 + r) * (3 * CC) + ch;
        cp16(sQ + so, qkv + go);
    }

    auto load_stage = [&](int sj) {
        int st = sj & 1;
        uint32_t base = sb + AQ_TILEB + st * (2 * AKV_TILEB);
#pragma unroll
        for (int i = 0; i < 4; i++) {
            int idx = tid + i * 256;
            int tile = idx >> 9;
            int rem = idx & 511;
            int r = rem >> 3, ch = (rem & 7) * 8;
            uint32_t so = base + tile * AKV_TILEB + (uint32_t)(r * AT_PITCH + ch) * 2;
            size_t gk = rowbase + (size_t)(sj * 64 + r) * (3 * CC) + CC + ch;
            if (tile == 0) cp16(so, qkv + gk);
            else           cp16(so, qkv + gk + CC);
        }
        if (tid < 16)
            cp16(sb + SMASK_OFF + st * 256 + tid * 16, gmask + sj * 64 + tid * 4);
    };

    int ns = 2 * qi + 2;
    load_stage(0);
    CP_COMMIT();

    float O[8][4];
#pragma unroll
    for (int j = 0; j < 8; j++)
#pragma unroll
        for (int e = 0; e < 4; e++) O[j][e] = 0.0f;
    float lsum0 = 0.0f, lsum1 = 0.0f;

    const float csc = 0.0450842200f;   // log2(e) / 32
    const int t_base = qi * 128 + wq + (lane >> 2);

    for (int sj = 0; sj < ns; sj++) {
        int cur = sj & 1;
        if (sj + 1 < ns) {
            load_stage(sj + 1);
            CP_COMMIT();
            CP_WAIT1();
        } else {
            CP_WAIT0();
        }
        __syncthreads();

        uint32_t kvb = sb + AQ_TILEB + cur * (2 * AKV_TILEB);
        uint32_t sK = kvb, sV = kvb + AKV_TILEB;
        const int* mrow = smask + cur * 64;

        // S = Q K^T (single pass)
        float S[8][4];
#pragma unroll
        for (int j = 0; j < 8; j++)
#pragma unroll
            for (int e = 0; e < 4; e++) S[j][e] = 0.0f;

#pragma unroll
        for (int ks = 0; ks < 4; ks++) {
            uint32_t qa[4];
            uint32_t ad = sQ + (uint32_t)((wq + lrow) * AT_PITCH + ks * 16 + lkc) * 2;
            LDSM4(qa, ad);
#pragma unroll
            for (int nj = 0; nj < 4; nj++) {
                uint32_t bd = sK + (uint32_t)((nj * 16 + lrow) * AT_PITCH + ks * 16 + lkc) * 2;
                uint32_t th[4];
                LDSM4(th, bd);
                uint32_t bh0[2] = {th[0], th[2]}, bh1[2] = {th[1], th[3]};
                mma16816(S[2 * nj],     qa, bh0);
                mma16816(S[2 * nj + 1], qa, bh1);
            }
        }

        // mask + exp2 + pack P (hi only)
        uint32_t aP[8][2];
#pragma unroll
        for (int j = 0; j < 8; j++) {
            int s0 = j * 8 + (lane & 3) * 2;
#pragma unroll
            for (int e = 0; e < 4; e++) {
                int s_l = s0 + (e & 1);
                int s_g = sj * 64 + s_l;
                int t_g = t_base + (e >> 1) * 8;
                float v = S[j][e] * csc;
                if (mrow[s_l] || (s_g > t_g)) v = -1e9f;
                S[j][e] = fex2(v);
            }
            lsum0 += S[j][0] + S[j][1];
            lsum1 += S[j][2] + S[j][3];
            __half2 h0 = __floats2half2_rn(S[j][0], S[j][1]);
            __half2 h1 = __floats2half2_rn(S[j][2], S[j][3]);
            aP[j][0] = *(uint32_t*)&h0;
            aP[j][1] = *(uint32_t*)&h1;
        }

        // O += P V (single pass)
#pragma unroll
        for (int kc = 0; kc < 4; kc++) {
            uint32_t Af[4] = {aP[2 * kc][0], aP[2 * kc][1],
                              aP[2 * kc + 1][0], aP[2 * kc + 1][1]};
#pragma unroll
            for (int dj = 0; dj < 4; dj++) {
                uint32_t vd = sV + (uint32_t)((kc * 16 + lrow) * AT_PITCH + dj * 16 + lkc) * 2;
                uint32_t tv[4];
                LDSM4T(tv, vd);
                uint32_t b0[2] = {tv[0], tv[1]}, b1[2] = {tv[2], tv[3]};
                mma16816(O[2 * dj],     Af, b0);
                mma16816(O[2 * dj + 1], Af, b1);
            }
        }
        __syncthreads();
    }

    // finalize
    lsum0 += __shfl_xor_sync(0xffffffffu, lsum0, 1);
    lsum0 += __shfl_xor_sync(0xffffffffu, lsum0, 2);
    lsum1 += __shfl_xor_sync(0xffffffffu, lsum1, 1);
    lsum1 += __shfl_xor_sync(0xffffffffu, lsum1, 2);
    float inv0 = 1.0f / lsum0;
    float inv1 = 1.0f / lsum1;

#pragma unroll
    for (int hh = 0; hh < 2; hh++) {
        float inv = hh ? inv1 : inv0;
        size_t orow = (size_t)(b * TT + t_base + hh * 8) * CC + h * DD + (lane & 3) * 2;
#pragma unroll
        for (int j = 0; j < 8; j++) {
            float v0 = O[j][hh * 2 + 0] * inv;
            float v1 = O[j][hh * 2 + 1] * inv;
            *(__half2*)(outp + orow + j * 8) = __floats2half2_rn(v0, v1);
        }
    }
}

// ---------------------------------------------------------------------------
// Fixup: rows t < first_unpadded[b] -> out = mean of V over padded positions.
// ---------------------------------------------------------------------------
__global__ __launch_bounds__(256) void fixup_kernel(
    const __half* __restrict__ qkv,
    const int* __restrict__ mask,
    __half* __restrict__ outp)
{
    int b = blockIdx.x;
    int f = g_fu[b];
    if (f == 0) return;
    int tid = threadIdx.x;
    float sum[4] = {0, 0, 0, 0};
    int cnt = 0;
    for (int s = 0; s < TT; s++) {
        if (mask[b * TT + s]) {
            cnt++;
            size_t base = (size_t)(b * TT + s) * (3 * CC) + 2 * CC + tid * 4;
#pragma unroll
            for (int e = 0; e < 4; e++)
                sum[e] += __half2float(qkv[base + e]);
        }
    }
    float invc = 1.0f / (float)cnt;
    __half mh[4];
#pragma unroll
    for (int e = 0; e < 4; e++) mh[e] = __float2half_rn(sum[e] * invc);
    for (int t = 0; t < f; t++) {
        size_t o = (size_t)(b * TT + t) * CC + tid * 4;
#pragma unroll
        for (int e = 0; e < 4; e++)
            outp[o + e] = mh[e];
    }
}

// ---------------------------------------------------------------------------
// Launch
// ---------------------------------------------------------------------------
extern "C" void kernel_launch(void* const* d_in, const int* in_sizes, int n_in,
                              void* d_out, int out_size)
{
    const float* x     = (const float*)d_in[0];
    const void*  pmask = d_in[1];
    const float* Wq    = (const float*)d_in[2];
    const float* Wk    = (const float*)d_in[3];
    const float* Wv    = (const float*)d_in[4];
    const float* Wo    = (const float*)d_in[5];
    const float* bo    = (const float*)d_in[6];
    const float* ln1_g = (const float*)d_in[7];
    const float* ln1_b = (const float*)d_in[8];
    const float* ln2_g = (const float*)d_in[9];
    const float* ln2_b = (const float*)d_in[10];
    const float* W1    = (const float*)d_in[11];
    const float* b1    = (const float*)d_in[12];
    const float* W2    = (const float*)d_in[13];
    const float* b2    = (const float*)d_in[14];
    float* out = (float*)d_out;

    void *p_proj, *p_qkv, *p_h, *p_at, *p_h2, *p_f1,
         *p_wq, *p_wo, *p_w1, *p_w2, *p_mask;
    cudaGetSymbolAddress(&p_proj, g_proj);
    cudaGetSymbolAddress(&p_qkv,  g_qkv);
    cudaGetSymbolAddress(&p_h,    g_h);
    cudaGetSymbolAddress(&p_at,   g_at);
    cudaGetSymbolAddress(&p_h2,   g_h2);
    cudaGetSymbolAddress(&p_f1,   g_f1);
    cudaGetSymbolAddress(&p_wq,   g_wq);
    cudaGetSymbolAddress(&p_wo,   g_wo);
    cudaGetSymbolAddress(&p_w1,   g_w1);
    cudaGetSymbolAddress(&p_w2,   g_w2);
    cudaGetSymbolAddress(&p_mask, g_mask);

    cudaFuncSetAttribute(gemm_mma, cudaFuncAttributeMaxDynamicSharedMemorySize, GEMM_SMEM);
    cudaFuncSetAttribute(attn_mma, cudaFuncAttributeMaxDynamicSharedMemorySize, ATT_SMEM);

    // 1. mask + first-unpadded
    mask_expand_kernel<<<1, 256>>>(pmask, (int*)p_mask);
    // 2. weight prep (fp16)
    pack_qkv_kernel<<<(3 * CC * CC + 255) / 256, 256>>>(Wq, Wk, Wv, (__half*)p_wq);
    tsplit_kernel<<<dim3(CC / 32, CC / 32), dim3(32, 8)>>>(Wo, (__half*)p_wo, CC, CC);
    tsplit_kernel<<<dim3(FF / 32, CC / 32), dim3(32, 8)>>>(W1, (__half*)p_w1, CC, FF);
    tsplit_kernel<<<dim3(CC / 32, FF / 32), dim3(32, 8)>>>(W2, (__half*)p_w2, FF, CC);
    // 3. LN1 (hi only)
    ln_kernel<<<MR, 256>>>(x, ln1_g, ln1_b, (__half*)p_h);
    // 4. QKV gemm (1-pass)
    gemm_mma<<<dim3(3 * CC / 256, MR / 128), 256, GEMM_SMEM>>>(
        (__half*)p_h, (__half*)p_wq, nullptr,
        nullptr, (__half*)p_qkv, 3 * CC, CC, 0);
    // 5. flash attention + fixup
    attn_mma<<<dim3(TT / 128, BB * HH), 256, ATT_SMEM>>>(
        (const __half*)p_qkv, (const int*)p_mask, (__half*)p_at);
    fixup_kernel<<<BB, 256>>>(
        (const __half*)p_qkv, (const int*)p_mask, (__half*)p_at);
    // 6. Wo projection (1-pass) -> fp32 proj
    gemm_mma<<<dim3(CC / 256, MR / 128), 256, GEMM_SMEM>>>(
        (__half*)p_at, (__half*)p_wo, bo,
        (float*)p_proj, nullptr, CC, CC, 0);
    // 7. LN2 (hi only)
    ln_kernel<<<MR, 256>>>((const float*)p_proj, ln2_g, ln2_b, (__half*)p_h2);
    // 8. FFN1 + relu (1-pass)
    gemm_mma<<<dim3(FF / 256, MR / 128), 256, GEMM_SMEM>>>(
        (__half*)p_h2, (__half*)p_w1, b1,
        nullptr, (__half*)p_f1, FF, CC, 1);
    // 9. FFN2 -> d_out (1-pass)
    gemm_mma<<<dim3(CC / 256, MR / 128), 256, GEMM_SMEM>>>(
        (__half*)p_f1, (__half*)p_w2, b2,
        out, nullptr, CC, FF, 0);
}

// round 14
// speedup vs baseline: 1.9290x; 1.0216x over previous
#include <cuda_runtime.h>
#include <cuda_fp16.h>
#include <cstdint>
#include <math.h>

// Problem dims
#define BB 4
#define TT 1024
#define CC 1024
#define HH 16
#define DD 64
#define FF 4096
#define MR 4096   // B*T

// ---------------------------------------------------------------------------
// Scratch (static device globals)
// ---------------------------------------------------------------------------
__device__ __align__(256) __half g_qkv[MR * 3 * CC];
__device__ __align__(256) __half g_h  [MR * CC];   // LN1 out; reused for proj fp16
__device__ __align__(256) __half g_at [MR * CC];
__device__ __align__(256) __half g_h2 [MR * CC];
__device__ __align__(256) __half g_f1 [MR * FF];
__device__ __align__(256) __half g_wq [3 * CC * CC];
__device__ __align__(256) __half g_wo [CC * CC];
__device__ __align__(256) __half g_w1 [FF * CC];
__device__ __align__(256) __half g_w2 [CC * FF];
__device__ int g_mask[MR];
__device__ int g_fu[BB];

// ---------------------------------------------------------------------------
// Helpers
// ---------------------------------------------------------------------------
__device__ __forceinline__ uint32_t smem_u32(const void* p) {
    uint32_t a;
    asm("{ .reg .u64 t; cvta.to.shared.u64 t, %1; cvt.u32.u64 %0, t; }" : "=r"(a) : "l"(p));
    return a;
}
__device__ __forceinline__ void cp16(uint32_t s, const void* g) {
    asm volatile("cp.async.cg.shared.global [%0], [%1], 16;" :: "r"(s), "l"(g));
}
#define CP_COMMIT() asm volatile("cp.async.commit_group;" ::: "memory")
#define CP_WAIT3()  asm volatile("cp.async.wait_group 3;"  ::: "memory")
#define CP_WAIT1()  asm volatile("cp.async.wait_group 1;"  ::: "memory")
#define CP_WAIT0()  asm volatile("cp.async.wait_group 0;"  ::: "memory")

#define LDSM4(r, addr) \
    asm volatile("ldmatrix.sync.aligned.m8n8.x4.shared.b16 {%0,%1,%2,%3}, [%4];" \
        : "=r"((r)[0]), "=r"((r)[1]), "=r"((r)[2]), "=r"((r)[3]) : "r"(addr))
#define LDSM4T(r, addr) \
    asm volatile("ldmatrix.sync.aligned.m8n8.x4.trans.shared.b16 {%0,%1,%2,%3}, [%4];" \
        : "=r"((r)[0]), "=r"((r)[1]), "=r"((r)[2]), "=r"((r)[3]) : "r"(addr))

__device__ __forceinline__ void mma16816(float* c, const uint32_t* a, const uint32_t* b) {
    asm volatile("mma.sync.aligned.m16n8k16.row.col.f32.f16.f16.f32 "
        "{%0,%1,%2,%3}, {%4,%5,%6,%7}, {%8,%9}, {%0,%1,%2,%3};"
        : "+f"(c[0]), "+f"(c[1]), "+f"(c[2]), "+f"(c[3])
        : "r"(a[0]), "r"(a[1]), "r"(a[2]), "r"(a[3]), "r"(b[0]), "r"(b[1]));
}

__device__ __forceinline__ float fex2(float x) {
    float r;
    asm("ex2.approx.ftz.f32 %0, %1;" : "=f"(r) : "f"(x));
    return r;
}

// ---------------------------------------------------------------------------
// Mask classify + expand + first-unpadded per batch
// ---------------------------------------------------------------------------
__global__ void mask_expand_kernel(const void* __restrict__ pm, int* __restrict__ out)
{
    int tid = threadIdx.x;
    if (tid < BB) g_fu[tid] = TT;
    const unsigned* w = (const unsigned*)pm;
    int li = 0, lf = 0;
    for (int i = tid; i < 1024; i += 256) {
        unsigned v = w[i];
        li |= (v > 1u);
        lf |= (v != 0u && v != 0x3F800000u);
    }
    int not_int = __syncthreads_or(li);
    int not_flt = __syncthreads_or(lf);
    int cls = (!not_int) ? 0 : ((!not_flt) ? 1 : 2);
    for (int i = tid; i < MR; i += 256) {
        int m;
        if (cls == 0)      m = (((const int*)pm)[i] != 0);
        else if (cls == 1) m = (((const float*)pm)[i] != 0.0f);
        else               m = (((const unsigned char*)pm)[i] != 0);
        out[i] = m;
        if (!m) atomicMin(&g_fu[i >> 10], i & 1023);
    }
}

// ---------------------------------------------------------------------------
// Pack Wq/Wk/Wv (H,C,D) -> transposed (3C, C) fp16
// ---------------------------------------------------------------------------
__global__ void pack_qkv_kernel(const float* __restrict__ Wq,
                                const float* __restrict__ Wk,
                                const float* __restrict__ Wv,
                                __half* __restrict__ oh)
{
    int idx = blockIdx.x * blockDim.x + threadIdx.x;
    if (idx >= 3 * CC * CC) return;
    int j = idx / CC;
    int c = idx % CC;
    const float* W = (j < CC) ? Wq : (j < 2 * CC) ? Wk : Wv;
    int jj = j & (CC - 1);
    int h = jj >> 6, d = jj & 63;
    oh[idx] = __float2half_rn(W[(h * CC + c) * DD + d]);
}

// ---------------------------------------------------------------------------
// Tiled transpose: in (R, Cn) fp32 -> out (Cn, R) fp16
// ---------------------------------------------------------------------------
__global__ void tsplit_kernel(const float* __restrict__ in,
                              __half* __restrict__ oh,
                              int R, int Cn)
{
    __shared__ float t[32][33];
    int c0 = blockIdx.x * 32, r0 = blockIdx.y * 32;
    int x = threadIdx.x, y = threadIdx.y;
#pragma unroll
    for (int i = 0; i < 32; i += 8)
        t[y + i][x] = in[(size_t)(r0 + y + i) * Cn + c0 + x];
    __syncthreads();
#pragma unroll
    for (int i = 0; i < 32; i += 8)
        oh[(size_t)(c0 + y + i) * R + r0 + x] = __float2half_rn(t[x][y + i]);
}

// ---------------------------------------------------------------------------
// LayerNorm (fp32 input) -> fp16
// ---------------------------------------------------------------------------
__global__ __launch_bounds__(256) void ln_kernel(const float* __restrict__ x,
                                                 const float* __restrict__ g,
                                                 const float* __restrict__ b,
                                                 __half* __restrict__ oh)
{
    int row = blockIdx.x, tid = threadIdx.x;
    const float* xr = x + (size_t)row * CC;
    float v[4];
    float s = 0.f, ss = 0.f;
#pragma unroll
    for (int i = 0; i < 4; i++) {
        v[i] = xr[tid + i * 256];
        s += v[i];
        ss += v[i] * v[i];
    }
#pragma unroll
    for (int o = 16; o; o >>= 1) {
        s  += __shfl_xor_sync(0xffffffffu, s,  o);
        ss += __shfl_xor_sync(0xffffffffu, ss, o);
    }
    __shared__ float ws[8], wss[8];
    __shared__ float s_m, s_r;
    int wid = tid >> 5;
    if ((tid & 31) == 0) { ws[wid] = s; wss[wid] = ss; }
    __syncthreads();
    if (tid == 0) {
        float S = 0.f, SS = 0.f;
        for (int i = 0; i < 8; i++) { S += ws[i]; SS += wss[i]; }
        float m = S * (1.0f / CC);
        float var = SS * (1.0f / CC) - m * m;
        s_m = m;
        s_r = rsqrtf(var + 1e-5f);
    }
    __syncthreads();
    float m = s_m, r = s_r;
#pragma unroll
    for (int i = 0; i < 4; i++) {
        int c = tid + i * 256;
        float o = (v[i] - m) * r * g[c] + b[c];
        oh[(size_t)row * CC + c] = __float2half_rn(o);
    }
}

// ---------------------------------------------------------------------------
// LayerNorm (fp16 input) -> fp16
// ---------------------------------------------------------------------------
__global__ __launch_bounds__(256) void ln_h_kernel(const __half* __restrict__ x,
                                                   const float* __restrict__ g,
                                                   const float* __restrict__ b,
                                                   __half* __restrict__ oh)
{
    int row = blockIdx.x, tid = threadIdx.x;
    const __half* xr = x + (size_t)row * CC;
    float v[4];
    float s = 0.f, ss = 0.f;
#pragma unroll
    for (int i = 0; i < 4; i++) {
        v[i] = __half2float(xr[tid + i * 256]);
        s += v[i];
        ss += v[i] * v[i];
    }
#pragma unroll
    for (int o = 16; o; o >>= 1) {
        s  += __shfl_xor_sync(0xffffffffu, s,  o);
        ss += __shfl_xor_sync(0xffffffffu, ss, o);
    }
    __shared__ float ws[8], wss[8];
    __shared__ float s_m, s_r;
    int wid = tid >> 5;
    if ((tid & 31) == 0) { ws[wid] = s; wss[wid] = ss; }
    __syncthreads();
    if (tid == 0) {
        float S = 0.f, SS = 0.f;
        for (int i = 0; i < 8; i++) { S += ws[i]; SS += wss[i]; }
        float m = S * (1.0f / CC);
        float var = SS * (1.0f / CC) - m * m;
        s_m = m;
        s_r = rsqrtf(var + 1e-5f);
    }
    __syncthreads();
    float m = s_m, r = s_r;
#pragma unroll
    for (int i = 0; i < 4; i++) {
        int c = tid + i * 256;
        float o = (v[i] - m) * r * g[c] + b[c];
        oh[(size_t)row * CC + c] = __float2half_rn(o);
    }
}

// ---------------------------------------------------------------------------
// fp16 1-pass GEMM: D = Ah(M,K) @ Bh^T, B stored (N,K) fp16.
// CTA 128x256, 256 threads / 8 warps (warp tile 64x64), K-chunk 64,
// 4-stage cp.async pipeline (3-deep prefetch).
// ---------------------------------------------------------------------------
#define PITCH 72
#define A_TILE_B (128 * PITCH * 2)          // 18432
#define B_TILE_B (256 * PITCH * 2)          // 36864
#define STAGE_B (A_TILE_B + B_TILE_B)       // 55296
#define NSTAGE 4
#define GEMM_SMEM (NSTAGE * STAGE_B)        // 221184

__global__ __launch_bounds__(256, 1) void gemm_mma(
    const __half* __restrict__ Ah,
    const __half* __restrict__ Bh,
    const float* __restrict__ bias,
    float* __restrict__ outF,
    __half* __restrict__ outH,
    int Ntot, int Ktot, int relu)
{
    extern __shared__ __align__(128) char smem[];
    const uint32_t sb0 = smem_u32(smem);
    int tid = threadIdx.x, lane = tid & 31, w = tid >> 5;
    int bm = blockIdx.y * 128, bn = blockIdx.x * 256;
    int wm = (w & 1) * 64, wn = (w >> 1) * 64;
    int nk = Ktot >> 6;

    float acc[4][8][4];
#pragma unroll
    for (int i = 0; i < 4; i++)
#pragma unroll
        for (int j = 0; j < 8; j++)
#pragma unroll
            for (int e = 0; e < 4; e++) acc[i][j][e] = 0.0f;

    auto load_stage = [&](int st, int kc) {
        uint32_t sb = sb0 + st * STAGE_B;
#pragma unroll
        for (int i = 0; i < 12; i++) {
            int idx = tid + i * 256;          // 0..3071
            int c = (idx & 7) * 8;
            if (idx < 1024) {                 // Ah
                int r = idx >> 3;
                cp16(sb + (uint32_t)(r * PITCH + c) * 2,
                     Ah + (size_t)(bm + r) * Ktot + kc + c);
            } else {                          // Bh
                int r = (idx - 1024) >> 3;
                cp16(sb + A_TILE_B + (uint32_t)(r * PITCH + c) * 2,
                     Bh + (size_t)(bn + r) * Ktot + kc + c);
            }
        }
    };

    // preload 3 stages (nk >= 16 always here)
    load_stage(0, 0);  CP_COMMIT();
    load_stage(1, 64); CP_COMMIT();
    load_stage(2, 128); CP_COMMIT();

    int lrow = lane & 15;
    int lk = (lane >> 4) * 8;

    for (int kc = 0; kc < nk; kc++) {
        if (kc + 3 < nk) {
            load_stage((kc + 3) & 3, (kc + 3) * 64);
            CP_COMMIT();
            CP_WAIT3();
        } else {
            CP_WAIT0();
        }
        __syncthreads();

        uint32_t sb = sb0 + (kc & 3) * STAGE_B;
#pragma unroll
        for (int ks = 0; ks < 4; ks++) {
            int k0 = ks * 16;
            uint32_t ah[4][4], bh[8][2];
#pragma unroll
            for (int i = 0; i < 4; i++) {
                uint32_t ad = sb + (uint32_t)((wm + i * 16 + lrow) * PITCH + k0 + lk) * 2;
                LDSM4(ah[i], ad);
            }
#pragma unroll
            for (int jj = 0; jj < 4; jj++) {
                uint32_t bd = sb + A_TILE_B +
                              (uint32_t)((wn + jj * 16 + lrow) * PITCH + k0 + lk) * 2;
                uint32_t t[4];
                LDSM4(t, bd);
                bh[jj * 2][0] = t[0]; bh[jj * 2][1] = t[2];
                bh[jj * 2 + 1][0] = t[1]; bh[jj * 2 + 1][1] = t[3];
            }
#pragma unroll
            for (int i = 0; i < 4; i++)
#pragma unroll
                for (int j = 0; j < 8; j++)
                    mma16816(acc[i][j], ah[i], bh[j]);
        }
        __syncthreads();
    }

#pragma unroll
    for (int i = 0; i < 4; i++) {
        int r0 = bm + wm + i * 16 + (lane >> 2);
#pragma unroll
        for (int j = 0; j < 8; j++) {
            int c = bn + wn + j * 8 + (lane & 3) * 2;
            float bx0 = bias ? bias[c] : 0.0f;
            float bx1 = bias ? bias[c + 1] : 0.0f;
#pragma unroll
            for (int hh = 0; hh < 2; hh++) {
                int r = r0 + hh * 8;
                float v0 = acc[i][j][hh * 2 + 0] + bx0;
                float v1 = acc[i][j][hh * 2 + 1] + bx1;
                if (relu) { v0 = fmaxf(v0, 0.0f); v1 = fmaxf(v1, 0.0f); }
                size_t o = (size_t)r * Ntot + c;
                if (outF) {
                    outF[o] = v0;
                    outF[o + 1] = v1;
                } else {
                    *(__half2*)(outH + o) = __floats2half2_rn(v0, v1);
                }
            }
        }
    }
}

// ---------------------------------------------------------------------------
// fp16 flash attention: single-pass QK, single-pass PV.
// CTA 256 thr (8 warps), q-tile 128, s-tile 64, causal-only sweep,
// double-buffered cp.async over {Kh, Vh, mask}; heavy blocks first.
// ---------------------------------------------------------------------------
#define AT_PITCH 72
#define AQ_TILEB (128 * AT_PITCH * 2)     // 18432
#define AKV_TILEB (64 * AT_PITCH * 2)     // 9216
#define SMASK_OFF (AQ_TILEB + 4 * AKV_TILEB)       // 55296
#define ATT_SMEM (SMASK_OFF + 2 * 64 * 4)          // 55808

__global__ __launch_bounds__(256) void attn_mma(
    const __half* __restrict__ qkv,
    const int* __restrict__ mask,
    __half* __restrict__ outp)
{
    extern __shared__ __align__(128) char smem[];
    const uint32_t sb = smem_u32(smem);
    const uint32_t sQ = sb;

    int qi = (int)gridDim.x - 1 - (int)blockIdx.x;   // heavy blocks first
    int bh = blockIdx.y;
    int b = bh >> 4, h = bh & 15;
    int tid = threadIdx.x, lane = tid & 31, w = tid >> 5;
    int wq = w * 16;
    int lrow = lane & 15, lkc = (lane >> 4) * 8;

    const size_t rowbase = (size_t)(b * TT) * (3 * CC) + h * DD;
    const int* gmask = mask + b * TT;
    int* smask = (int*)(smem + SMASK_OFF);

    // Q tile
#pragma unroll
    for (int i = 0; i < 4; i++) {
        int idx = tid + i * 256;
        int r = idx >> 3, ch = (idx & 7) * 8;
        uint32_t so = (uint32_t)(r * AT_PITCH + ch) * 2;
        size_t go = rowbase + (size_t)(qi * 128 + r) * (3 * CC) + ch;
        cp16(sQ + so, qkv + go);
    }

    auto load_stage = [&](int sj) {
        int st = sj & 1;
        uint32_t base = sb + AQ_TILEB + st * (2 * AKV_TILEB);
#pragma unroll
        for (int i = 0; i < 4; i++) {
            int idx = tid + i * 256;
            int tile = idx >> 9;
            int rem = idx & 511;
            int r = rem >> 3, ch = (rem & 7) * 8;
            uint32_t so = base + tile * AKV_TILEB + (uint32_t)(r * AT_PITCH + ch) * 2;
            size_t gk = rowbase + (size_t)(sj * 64 + r) * (3 * CC) + CC + ch;
            if (tile == 0) cp16(so, qkv + gk);
            else           cp16(so, qkv + gk + CC);
        }
        if (tid < 16)
            cp16(sb + SMASK_OFF + st * 256 + tid * 16, gmask + sj * 64 + tid * 4);
    };

    int ns = 2 * qi + 2;
    load_stage(0);
    CP_COMMIT();

    float O[8][4];
#pragma unroll
    for (int j = 0; j < 8; j++)
#pragma unroll
        for (int e = 0; e < 4; e++) O[j][e] = 0.0f;
    float lsum0 = 0.0f, lsum1 = 0.0f;

    const float csc = 0.0450842200f;   // log2(e) / 32
    const int t_base = qi * 128 + wq + (lane >> 2);

    for (int sj = 0; sj < ns; sj++) {
        int cur = sj & 1;
        if (sj + 1 < ns) {
            load_stage(sj + 1);
            CP_COMMIT();
            CP_WAIT1();
        } else {
            CP_WAIT0();
        }
        __syncthreads();

        uint32_t kvb = sb + AQ_TILEB + cur * (2 * AKV_TILEB);
        uint32_t sK = kvb, sV = kvb + AKV_TILEB;
        const int* mrow = smask + cur * 64;

        // S = Q K^T (single pass)
        float S[8][4];
#pragma unroll
        for (int j = 0; j < 8; j++)
#pragma unroll
            for (int e = 0; e < 4; e++) S[j][e] = 0.0f;

#pragma unroll
        for (int ks = 0; ks < 4; ks++) {
            uint32_t qa[4];
            uint32_t ad = sQ + (uint32_t)((wq + lrow) * AT_PITCH + ks * 16 + lkc) * 2;
            LDSM4(qa, ad);
#pragma unroll
            for (int nj = 0; nj < 4; nj++) {
                uint32_t bd = sK + (uint32_t)((nj * 16 + lrow) * AT_PITCH + ks * 16 + lkc) * 2;
                uint32_t th[4];
                LDSM4(th, bd);
                uint32_t bh0[2] = {th[0], th[2]}, bh1[2] = {th[1], th[3]};
                mma16816(S[2 * nj],     qa, bh0);
                mma16816(S[2 * nj + 1], qa, bh1);
            }
        }

        // mask + exp2 + pack P
        uint32_t aP[8][2];
#pragma unroll
        for (int j = 0; j < 8; j++) {
            int s0 = j * 8 + (lane & 3) * 2;
#pragma unroll
            for (int e = 0; e < 4; e++) {
                int s_l = s0 + (e & 1);
                int s_g = sj * 64 + s_l;
                int t_g = t_base + (e >> 1) * 8;
                float v = S[j][e] * csc;
                if (mrow[s_l] || (s_g > t_g)) v = -1e9f;
                S[j][e] = fex2(v);
            }
            lsum0 += S[j][0] + S[j][1];
            lsum1 += S[j][2] + S[j][3];
            __half2 h0 = __floats2half2_rn(S[j][0], S[j][1]);
            __half2 h1 = __floats2half2_rn(S[j][2], S[j][3]);
            aP[j][0] = *(uint32_t*)&h0;
            aP[j][1] = *(uint32_t*)&h1;
        }

        // O += P V (single pass)
#pragma unroll
        for (int kc = 0; kc < 4; kc++) {
            uint32_t Af[4] = {aP[2 * kc][0], aP[2 * kc][1],
                              aP[2 * kc + 1][0], aP[2 * kc + 1][1]};
#pragma unroll
            for (int dj = 0; dj < 4; dj++) {
                uint32_t vd = sV + (uint32_t)((kc * 16 + lrow) * AT_PITCH + dj * 16 + lkc) * 2;
                uint32_t tv[4];
                LDSM4T(tv, vd);
                uint32_t b0[2] = {tv[0], tv[1]}, b1[2] = {tv[2], tv[3]};
                mma16816(O[2 * dj],     Af, b0);
                mma16816(O[2 * dj + 1], Af, b1);
            }
        }
        __syncthreads();
    }

    // finalize
    lsum0 += __shfl_xor_sync(0xffffffffu, lsum0, 1);
    lsum0 += __shfl_xor_sync(0xffffffffu, lsum0, 2);
    lsum1 += __shfl_xor_sync(0xffffffffu, lsum1, 1);
    lsum1 += __shfl_xor_sync(0xffffffffu, lsum1, 2);
    float inv0 = 1.0f / lsum0;
    float inv1 = 1.0f / lsum1;

#pragma unroll
    for (int hh = 0; hh < 2; hh++) {
        float inv = hh ? inv1 : inv0;
        size_t orow = (size_t)(b * TT + t_base + hh * 8) * CC + h * DD + (lane & 3) * 2;
#pragma unroll
        for (int j = 0; j < 8; j++) {
            float v0 = O[j][hh * 2 + 0] * inv;
            float v1 = O[j][hh * 2 + 1] * inv;
            *(__half2*)(outp + orow + j * 8) = __floats2half2_rn(v0, v1);
        }
    }
}

// ---------------------------------------------------------------------------
// Fixup: rows t < first_unpadded[b] -> out = mean of V over padded positions.
// ---------------------------------------------------------------------------
__global__ __launch_bounds__(256) void fixup_kernel(
    const __half* __restrict__ qkv,
    const int* __restrict__ mask,
    __half* __restrict__ outp)
{
    int b = blockIdx.x;
    int f = g_fu[b];
    if (f == 0) return;
    int tid = threadIdx.x;
    float sum[4] = {0, 0, 0, 0};
    int cnt = 0;
    for (int s = 0; s < TT; s++) {
        if (mask[b * TT + s]) {
            cnt++;
            size_t base = (size_t)(b * TT + s) * (3 * CC) + 2 * CC + tid * 4;
#pragma unroll
            for (int e = 0; e < 4; e++)
                sum[e] += __half2float(qkv[base + e]);
        }
    }
    float invc = 1.0f / (float)cnt;
    __half mh[4];
#pragma unroll
    for (int e = 0; e < 4; e++) mh[e] = __float2half_rn(sum[e] * invc);
    for (int t = 0; t < f; t++) {
        size_t o = (size_t)(b * TT + t) * CC + tid * 4;
#pragma unroll
        for (int e = 0; e < 4; e++)
            outp[o + e] = mh[e];
    }
}

// ---------------------------------------------------------------------------
// Launch. Weight transposes forked onto a side stream (capture-legal event
// fork/join) so they overlap LN1 + QKV + attention.
// ---------------------------------------------------------------------------
static cudaStream_t s_side = nullptr;
static cudaEvent_t  s_evF = nullptr, s_evJ = nullptr;

extern "C" void kernel_launch(void* const* d_in, const int* in_sizes, int n_in,
                              void* d_out, int out_size)
{
    const float* x     = (const float*)d_in[0];
    const void*  pmask = d_in[1];
    const float* Wq    = (const float*)d_in[2];
    const float* Wk    = (const float*)d_in[3];
    const float* Wv    = (const float*)d_in[4];
    const float* Wo    = (const float*)d_in[5];
    const float* bo    = (const float*)d_in[6];
    const float* ln1_g = (const float*)d_in[7];
    const float* ln1_b = (const float*)d_in[8];
    const float* ln2_g = (const float*)d_in[9];
    const float* ln2_b = (const float*)d_in[10];
    const float* W1    = (const float*)d_in[11];
    const float* b1    = (const float*)d_in[12];
    const float* W2    = (const float*)d_in[13];
    const float* b2    = (const float*)d_in[14];
    float* out = (float*)d_out;

    void *p_qkv, *p_h, *p_at, *p_h2, *p_f1,
         *p_wq, *p_wo, *p_w1, *p_w2, *p_mask;
    cudaGetSymbolAddress(&p_qkv,  g_qkv);
    cudaGetSymbolAddress(&p_h,    g_h);
    cudaGetSymbolAddress(&p_at,   g_at);
    cudaGetSymbolAddress(&p_h2,   g_h2);
    cudaGetSymbolAddress(&p_f1,   g_f1);
    cudaGetSymbolAddress(&p_wq,   g_wq);
    cudaGetSymbolAddress(&p_wo,   g_wo);
    cudaGetSymbolAddress(&p_w1,   g_w1);
    cudaGetSymbolAddress(&p_w2,   g_w2);
    cudaGetSymbolAddress(&p_mask, g_mask);

    cudaFuncSetAttribute(gemm_mma, cudaFuncAttributeMaxDynamicSharedMemorySize, GEMM_SMEM);
    cudaFuncSetAttribute(attn_mma, cudaFuncAttributeMaxDynamicSharedMemorySize, ATT_SMEM);

    // one-time side-stream setup (first call is the uncaptured correctness run)
    if (!s_side) {
        cudaStreamCreateWithFlags(&s_side, cudaStreamNonBlocking);
        cudaEventCreateWithFlags(&s_evF, cudaEventDisableTiming);
        cudaEventCreateWithFlags(&s_evJ, cudaEventDisableTiming);
    }

    // ---- fork: weight transposes on the side stream ----
    cudaEventRecord(s_evF, 0);
    cudaStreamWaitEvent(s_side, s_evF, 0);
    tsplit_kernel<<<dim3(CC / 32, CC / 32), dim3(32, 8), 0, s_side>>>(
        Wo, (__half*)p_wo, CC, CC);
    tsplit_kernel<<<dim3(FF / 32, CC / 32), dim3(32, 8), 0, s_side>>>(
        W1, (__half*)p_w1, CC, FF);
    tsplit_kernel<<<dim3(CC / 32, FF / 32), dim3(32, 8), 0, s_side>>>(
        W2, (__half*)p_w2, FF, CC);
    cudaEventRecord(s_evJ, s_side);

    // ---- main stream ----
    mask_expand_kernel<<<1, 256>>>(pmask, (int*)p_mask);
    pack_qkv_kernel<<<(3 * CC * CC + 255) / 256, 256>>>(Wq, Wk, Wv, (__half*)p_wq);
    ln_kernel<<<MR, 256>>>(x, ln1_g, ln1_b, (__half*)p_h);
    gemm_mma<<<dim3(3 * CC / 256, MR / 128), 256, GEMM_SMEM>>>(
        (__half*)p_h, (__half*)p_wq, nullptr,
        nullptr, (__half*)p_qkv, 3 * CC, CC, 0);
    attn_mma<<<dim3(TT / 128, BB * HH), 256, ATT_SMEM>>>(
        (const __half*)p_qkv, (const int*)p_mask, (__half*)p_at);
    fixup_kernel<<<BB, 256>>>(
        (const __half*)p_qkv, (const int*)p_mask, (__half*)p_at);

    // ---- join: weights ready ----
    cudaStreamWaitEvent(0, s_evJ, 0);

    // Wo projection (fp16 out, reusing g_h)
    gemm_mma<<<dim3(CC / 256, MR / 128), 256, GEMM_SMEM>>>(
        (__half*)p_at, (__half*)p_wo, bo,
        nullptr, (__half*)p_h, CC, CC, 0);
    // LN2 (fp16 input)
    ln_h_kernel<<<MR, 256>>>((const __half*)p_h, ln2_g, ln2_b, (__half*)p_h2);
    // FFN1 + relu
    gemm_mma<<<dim3(FF / 256, MR / 128), 256, GEMM_SMEM>>>(
        (__half*)p_h2, (__half*)p_w1, b1,
        nullptr, (__half*)p_f1, FF, CC, 1);
    // FFN2 -> d_out
    gemm_mma<<<dim3(CC / 256, MR / 128), 256, GEMM_SMEM>>>(
        (__half*)p_f1, (__half*)p_w2, b2,
        out, nullptr, CC, FF, 0);
}

// round 15
// speedup vs baseline: 1.9893x; 1.0312x over previous
#include <cuda_runtime.h>
#include <cuda_fp16.h>
#include <cstdint>
#include <math.h>

// Problem dims
#define BB 4
#define TT 1024
#define CC 1024
#define HH 16
#define DD 64
#define FF 4096
#define MR 4096   // B*T

// ---------------------------------------------------------------------------
// Scratch (static device globals)
// ---------------------------------------------------------------------------
__device__ __align__(256) __half g_qkv[MR * 3 * CC];
__device__ __align__(256) __half g_h  [MR * CC];   // LN1 out; reused for proj fp16
__device__ __align__(256) __half g_at [MR * CC];
__device__ __align__(256) __half g_h2 [MR * CC];
__device__ __align__(256) __half g_f1 [MR * FF];
__device__ __align__(256) __half g_wq [3 * CC * CC];
__device__ __align__(256) __half g_wo [CC * CC];
__device__ __align__(256) __half g_w1 [FF * CC];
__device__ __align__(256) __half g_w2 [CC * FF];
__device__ int g_mask[MR];
__device__ int g_fu[BB];

// ---------------------------------------------------------------------------
// Helpers
// ---------------------------------------------------------------------------
__device__ __forceinline__ uint32_t smem_u32(const void* p) {
    uint32_t a;
    asm("{ .reg .u64 t; cvta.to.shared.u64 t, %1; cvt.u32.u64 %0, t; }" : "=r"(a) : "l"(p));
    return a;
}
__device__ __forceinline__ void cp16(uint32_t s, const void* g) {
    asm volatile("cp.async.cg.shared.global [%0], [%1], 16;" :: "r"(s), "l"(g));
}
#define CP_COMMIT() asm volatile("cp.async.commit_group;" ::: "memory")
#define CP_WAIT3()  asm volatile("cp.async.wait_group 3;"  ::: "memory")
#define CP_WAIT1()  asm volatile("cp.async.wait_group 1;"  ::: "memory")
#define CP_WAIT0()  asm volatile("cp.async.wait_group 0;"  ::: "memory")

#define LDSM4(r, addr) \
    asm volatile("ldmatrix.sync.aligned.m8n8.x4.shared.b16 {%0,%1,%2,%3}, [%4];" \
        : "=r"((r)[0]), "=r"((r)[1]), "=r"((r)[2]), "=r"((r)[3]) : "r"(addr))
#define LDSM4T(r, addr) \
    asm volatile("ldmatrix.sync.aligned.m8n8.x4.trans.shared.b16 {%0,%1,%2,%3}, [%4];" \
        : "=r"((r)[0]), "=r"((r)[1]), "=r"((r)[2]), "=r"((r)[3]) : "r"(addr))

__device__ __forceinline__ void mma16816(float* c, const uint32_t* a, const uint32_t* b) {
    asm volatile("mma.sync.aligned.m16n8k16.row.col.f32.f16.f16.f32 "
        "{%0,%1,%2,%3}, {%4,%5,%6,%7}, {%8,%9}, {%0,%1,%2,%3};"
        : "+f"(c[0]), "+f"(c[1]), "+f"(c[2]), "+f"(c[3])
        : "r"(a[0]), "r"(a[1]), "r"(a[2]), "r"(a[3]), "r"(b[0]), "r"(b[1]));
}

__device__ __forceinline__ float fex2(float x) {
    float r;
    asm("ex2.approx.ftz.f32 %0, %1;" : "=f"(r) : "f"(x));
    return r;
}

// ---------------------------------------------------------------------------
// g_fu init (runs before mask_expand on side stream)
// ---------------------------------------------------------------------------
__global__ void fu_init_kernel()
{
    if (threadIdx.x < BB) g_fu[threadIdx.x] = TT;
}

// ---------------------------------------------------------------------------
// Mask classify + expand + first-unpadded per batch (16 blocks)
// ---------------------------------------------------------------------------
__global__ void mask_expand_kernel(const void* __restrict__ pm, int* __restrict__ out)
{
    int tid = threadIdx.x;
    const unsigned* w = (const unsigned*)pm;
    int li = 0, lf = 0;
    for (int i = tid; i < 1024; i += 256) {
        unsigned v = w[i];
        li |= (v > 1u);
        lf |= (v != 0u && v != 0x3F800000u);
    }
    int not_int = __syncthreads_or(li);
    int not_flt = __syncthreads_or(lf);
    int cls = (!not_int) ? 0 : ((!not_flt) ? 1 : 2);
    int i = blockIdx.x * 256 + tid;     // 16 blocks x 256 = 4096
    int m;
    if (cls == 0)      m = (((const int*)pm)[i] != 0);
    else if (cls == 1) m = (((const float*)pm)[i] != 0.0f);
    else               m = (((const unsigned char*)pm)[i] != 0);
    out[i] = m;
    if (!m) atomicMin(&g_fu[i >> 10], i & 1023);
}

// ---------------------------------------------------------------------------
// Tiled pack of Wq/Wk/Wv (H,C,D) -> transposed (3C, C) fp16, coalesced.
// Grid: 3 * 16 * 32 blocks. Block = (weight sel, head h, 32-wide c-chunk).
// Reads 32 rows x 64 d (contiguous 256B rows); writes 64 rows x 32 c.
// ---------------------------------------------------------------------------
__global__ void pack_qkv_kernel(const float* __restrict__ Wq,
                                const float* __restrict__ Wk,
                                const float* __restrict__ Wv,
                                __half* __restrict__ oh)
{
    __shared__ float t[32][65];
    int bid = blockIdx.x;
    int wsel = bid >> 9;            // /512
    int rem = bid & 511;
    int h = rem >> 5, ct = rem & 31;
    const float* W = (wsel == 0) ? Wq : (wsel == 1) ? Wk : Wv;
    int c0 = ct * 32;
    int x = threadIdx.x, y = threadIdx.y;   // 32 x 8

    const float* src = W + ((size_t)h * CC + c0) * DD;
#pragma unroll
    for (int i = 0; i < 4; i++) {
        int cc = y + i * 8;                  // 0..31
        t[cc][x]      = src[(size_t)cc * DD + x];
        t[cc][x + 32] = src[(size_t)cc * DD + x + 32];
    }
    __syncthreads();

    size_t obase = ((size_t)wsel * CC + h * DD) * CC + c0;
#pragma unroll
    for (int i = 0; i < 8; i++) {
        int d = y + i * 8;                   // 0..63
        oh[obase + (size_t)d * CC + x] = __float2half_rn(t[x][d]);
    }
}

// ---------------------------------------------------------------------------
// Tiled transpose: in (R, Cn) fp32 -> out (Cn, R) fp16
// ---------------------------------------------------------------------------
__global__ void tsplit_kernel(const float* __restrict__ in,
                              __half* __restrict__ oh,
                              int R, int Cn)
{
    __shared__ float t[32][33];
    int c0 = blockIdx.x * 32, r0 = blockIdx.y * 32;
    int x = threadIdx.x, y = threadIdx.y;
#pragma unroll
    for (int i = 0; i < 32; i += 8)
        t[y + i][x] = in[(size_t)(r0 + y + i) * Cn + c0 + x];
    __syncthreads();
#pragma unroll
    for (int i = 0; i < 32; i += 8)
        oh[(size_t)(c0 + y + i) * R + r0 + x] = __float2half_rn(t[x][y + i]);
}

// ---------------------------------------------------------------------------
// LayerNorm (fp32 input) -> fp16
// ---------------------------------------------------------------------------
__global__ __launch_bounds__(256) void ln_kernel(const float* __restrict__ x,
                                                 const float* __restrict__ g,
                                                 const float* __restrict__ b,
                                                 __half* __restrict__ oh)
{
    int row = blockIdx.x, tid = threadIdx.x;
    const float* xr = x + (size_t)row * CC;
    float v[4];
    float s = 0.f, ss = 0.f;
#pragma unroll
    for (int i = 0; i < 4; i++) {
        v[i] = xr[tid + i * 256];
        s += v[i];
        ss += v[i] * v[i];
    }
#pragma unroll
    for (int o = 16; o; o >>= 1) {
        s  += __shfl_xor_sync(0xffffffffu, s,  o);
        ss += __shfl_xor_sync(0xffffffffu, ss, o);
    }
    __shared__ float ws[8], wss[8];
    __shared__ float s_m, s_r;
    int wid = tid >> 5;
    if ((tid & 31) == 0) { ws[wid] = s; wss[wid] = ss; }
    __syncthreads();
    if (tid == 0) {
        float S = 0.f, SS = 0.f;
        for (int i = 0; i < 8; i++) { S += ws[i]; SS += wss[i]; }
        float m = S * (1.0f / CC);
        float var = SS * (1.0f / CC) - m * m;
        s_m = m;
        s_r = rsqrtf(var + 1e-5f);
    }
    __syncthreads();
    float m = s_m, r = s_r;
#pragma unroll
    for (int i = 0; i < 4; i++) {
        int c = tid + i * 256;
        float o = (v[i] - m) * r * g[c] + b[c];
        oh[(size_t)row * CC + c] = __float2half_rn(o);
    }
}

// ---------------------------------------------------------------------------
// LayerNorm (fp16 input) -> fp16
// ---------------------------------------------------------------------------
__global__ __launch_bounds__(256) void ln_h_kernel(const __half* __restrict__ x,
                                                   const float* __restrict__ g,
                                                   const float* __restrict__ b,
                                                   __half* __restrict__ oh)
{
    int row = blockIdx.x, tid = threadIdx.x;
    const __half* xr = x + (size_t)row * CC;
    float v[4];
    float s = 0.f, ss = 0.f;
#pragma unroll
    for (int i = 0; i < 4; i++) {
        v[i] = __half2float(xr[tid + i * 256]);
        s += v[i];
        ss += v[i] * v[i];
    }
#pragma unroll
    for (int o = 16; o; o >>= 1) {
        s  += __shfl_xor_sync(0xffffffffu, s,  o);
        ss += __shfl_xor_sync(0xffffffffu, ss, o);
    }
    __shared__ float ws[8], wss[8];
    __shared__ float s_m, s_r;
    int wid = tid >> 5;
    if ((tid & 31) == 0) { ws[wid] = s; wss[wid] = ss; }
    __syncthreads();
    if (tid == 0) {
        float S = 0.f, SS = 0.f;
        for (int i = 0; i < 8; i++) { S += ws[i]; SS += wss[i]; }
        float m = S * (1.0f / CC);
        float var = SS * (1.0f / CC) - m * m;
        s_m = m;
        s_r = rsqrtf(var + 1e-5f);
    }
    __syncthreads();
    float m = s_m, r = s_r;
#pragma unroll
    for (int i = 0; i < 4; i++) {
        int c = tid + i * 256;
        float o = (v[i] - m) * r * g[c] + b[c];
        oh[(size_t)row * CC + c] = __float2half_rn(o);
    }
}

// ---------------------------------------------------------------------------
// fp16 1-pass GEMM: D = Ah(M,K) @ Bh^T, B stored (N,K) fp16.
// CTA 128x256, 256 threads / 8 warps (warp tile 64x64), K-chunk 64,
// 4-stage cp.async pipeline (3-deep prefetch).
// ---------------------------------------------------------------------------
#define PITCH 72
#define A_TILE_B (128 * PITCH * 2)          // 18432
#define B_TILE_B (256 * PITCH * 2)          // 36864
#define STAGE_B (A_TILE_B + B_TILE_B)       // 55296
#define NSTAGE 4
#define GEMM_SMEM (NSTAGE * STAGE_B)        // 221184

__global__ __launch_bounds__(256, 1) void gemm_mma(
    const __half* __restrict__ Ah,
    const __half* __restrict__ Bh,
    const float* __restrict__ bias,
    float* __restrict__ outF,
    __half* __restrict__ outH,
    int Ntot, int Ktot, int relu)
{
    extern __shared__ __align__(128) char smem[];
    const uint32_t sb0 = smem_u32(smem);
    int tid = threadIdx.x, lane = tid & 31, w = tid >> 5;
    int bm = blockIdx.y * 128, bn = blockIdx.x * 256;
    int wm = (w & 1) * 64, wn = (w >> 1) * 64;
    int nk = Ktot >> 6;

    float acc[4][8][4];
#pragma unroll
    for (int i = 0; i < 4; i++)
#pragma unroll
        for (int j = 0; j < 8; j++)
#pragma unroll
            for (int e = 0; e < 4; e++) acc[i][j][e] = 0.0f;

    auto load_stage = [&](int st, int kc) {
        uint32_t sb = sb0 + st * STAGE_B;
#pragma unroll
        for (int i = 0; i < 12; i++) {
            int idx = tid + i * 256;          // 0..3071
            int c = (idx & 7) * 8;
            if (idx < 1024) {                 // Ah
                int r = idx >> 3;
                cp16(sb + (uint32_t)(r * PITCH + c) * 2,
                     Ah + (size_t)(bm + r) * Ktot + kc + c);
            } else {                          // Bh
                int r = (idx - 1024) >> 3;
                cp16(sb + A_TILE_B + (uint32_t)(r * PITCH + c) * 2,
                     Bh + (size_t)(bn + r) * Ktot + kc + c);
            }
        }
    };

    load_stage(0, 0);  CP_COMMIT();
    load_stage(1, 64); CP_COMMIT();
    load_stage(2, 128); CP_COMMIT();

    int lrow = lane & 15;
    int lk = (lane >> 4) * 8;

    for (int kc = 0; kc < nk; kc++) {
        if (kc + 3 < nk) {
            load_stage((kc + 3) & 3, (kc + 3) * 64);
            CP_COMMIT();
            CP_WAIT3();
        } else {
            CP_WAIT0();
        }
        __syncthreads();

        uint32_t sb = sb0 + (kc & 3) * STAGE_B;
#pragma unroll
        for (int ks = 0; ks < 4; ks++) {
            int k0 = ks * 16;
            uint32_t ah[4][4], bh[8][2];
#pragma unroll
            for (int i = 0; i < 4; i++) {
                uint32_t ad = sb + (uint32_t)((wm + i * 16 + lrow) * PITCH + k0 + lk) * 2;
                LDSM4(ah[i], ad);
            }
#pragma unroll
            for (int jj = 0; jj < 4; jj++) {
                uint32_t bd = sb + A_TILE_B +
                              (uint32_t)((wn + jj * 16 + lrow) * PITCH + k0 + lk) * 2;
                uint32_t t[4];
                LDSM4(t, bd);
                bh[jj * 2][0] = t[0]; bh[jj * 2][1] = t[2];
                bh[jj * 2 + 1][0] = t[1]; bh[jj * 2 + 1][1] = t[3];
            }
#pragma unroll
            for (int i = 0; i < 4; i++)
#pragma unroll
                for (int j = 0; j < 8; j++)
                    mma16816(acc[i][j], ah[i], bh[j]);
        }
        __syncthreads();
    }

#pragma unroll
    for (int i = 0; i < 4; i++) {
        int r0 = bm + wm + i * 16 + (lane >> 2);
#pragma unroll
        for (int j = 0; j < 8; j++) {
            int c = bn + wn + j * 8 + (lane & 3) * 2;
            float bx0 = bias ? bias[c] : 0.0f;
            float bx1 = bias ? bias[c + 1] : 0.0f;
#pragma unroll
            for (int hh = 0; hh < 2; hh++) {
                int r = r0 + hh * 8;
                float v0 = acc[i][j][hh * 2 + 0] + bx0;
                float v1 = acc[i][j][hh * 2 + 1] + bx1;
                if (relu) { v0 = fmaxf(v0, 0.0f); v1 = fmaxf(v1, 0.0f); }
                size_t o = (size_t)r * Ntot + c;
                if (outF) {
                    outF[o] = v0;
                    outF[o + 1] = v1;
                } else {
                    *(__half2*)(outH + o) = __floats2half2_rn(v0, v1);
                }
            }
        }
    }
}

// ---------------------------------------------------------------------------
// fp16 flash attention: single-pass QK, single-pass PV.
// ---------------------------------------------------------------------------
#define AT_PITCH 72
#define AQ_TILEB (128 * AT_PITCH * 2)     // 18432
#define AKV_TILEB (64 * AT_PITCH * 2)     // 9216
#define SMASK_OFF (AQ_TILEB + 4 * AKV_TILEB)       // 55296
#define ATT_SMEM (SMASK_OFF + 2 * 64 * 4)          // 55808

__global__ __launch_bounds__(256) void attn_mma(
    const __half* __restrict__ qkv,
    const int* __restrict__ mask,
    __half* __restrict__ outp)
{
    extern __shared__ __align__(128) char smem[];
    const uint32_t sb = smem_u32(smem);
    const uint32_t sQ = sb;

    int qi = (int)gridDim.x - 1 - (int)blockIdx.x;   // heavy blocks first
    int bh = blockIdx.y;
    int b = bh >> 4, h = bh & 15;
    int tid = threadIdx.x, lane = tid & 31, w = tid >> 5;
    int wq = w * 16;
    int lrow = lane & 15, lkc = (lane >> 4) * 8;

    const size_t rowbase = (size_t)(b * TT) * (3 * CC) + h * DD;
    const int* gmask = mask + b * TT;
    int* smask = (int*)(smem + SMASK_OFF);

    // Q tile
#pragma unroll
    for (int i = 0; i < 4; i++) {
        int idx = tid + i * 256;
        int r = idx >> 3, ch = (idx & 7) * 8;
        uint32_t so = (uint32_t)(r * AT_PITCH + ch) * 2;
        size_t go = rowbase + (size_t)(qi * 128 + r) * (3 * CC) + ch;
        cp16(sQ + so, qkv + go);
    }

    auto load_stage = [&](int sj) {
        int st = sj & 1;
        uint32_t base = sb + AQ_TILEB + st * (2 * AKV_TILEB);
#pragma unroll
        for (int i = 0; i < 4; i++) {
            int idx = tid + i * 256;
            int tile = idx >> 9;
            int rem = idx & 511;
            int r = rem >> 3, ch = (rem & 7) * 8;
            uint32_t so = base + tile * AKV_TILEB + (uint32_t)(r * AT_PITCH + ch) * 2;
            size_t gk = rowbase + (size_t)(sj * 64 + r) * (3 * CC) + CC + ch;
            if (tile == 0) cp16(so, qkv + gk);
            else           cp16(so, qkv + gk + CC);
        }
        if (tid < 16)
            cp16(sb + SMASK_OFF + st * 256 + tid * 16, gmask + sj * 64 + tid * 4);
    };

    int ns = 2 * qi + 2;
    load_stage(0);
    CP_COMMIT();

    float O[8][4];
#pragma unroll
    for (int j = 0; j < 8; j++)
#pragma unroll
        for (int e = 0; e < 4; e++) O[j][e] = 0.0f;
    float lsum0 = 0.0f, lsum1 = 0.0f;

    const float csc = 0.0450842200f;   // log2(e) / 32
    const int t_base = qi * 128 + wq + (lane >> 2);

    for (int sj = 0; sj < ns; sj++) {
        int cur = sj & 1;
        if (sj + 1 < ns) {
            load_stage(sj + 1);
            CP_COMMIT();
            CP_WAIT1();
        } else {
            CP_WAIT0();
        }
        __syncthreads();

        uint32_t kvb = sb + AQ_TILEB + cur * (2 * AKV_TILEB);
        uint32_t sK = kvb, sV = kvb + AKV_TILEB;
        const int* mrow = smask + cur * 64;

        // S = Q K^T (single pass)
        float S[8][4];
#pragma unroll
        for (int j = 0; j < 8; j++)
#pragma unroll
            for (int e = 0; e < 4; e++) S[j][e] = 0.0f;

#pragma unroll
        for (int ks = 0; ks < 4; ks++) {
            uint32_t qa[4];
            uint32_t ad = sQ + (uint32_t)((wq + lrow) * AT_PITCH + ks * 16 + lkc) * 2;
            LDSM4(qa, ad);
#pragma unroll
            for (int nj = 0; nj < 4; nj++) {
                uint32_t bd = sK + (uint32_t)((nj * 16 + lrow) * AT_PITCH + ks * 16 + lkc) * 2;
                uint32_t th[4];
                LDSM4(th, bd);
                uint32_t bh0[2] = {th[0], th[2]}, bh1[2] = {th[1], th[3]};
                mma16816(S[2 * nj],     qa, bh0);
                mma16816(S[2 * nj + 1], qa, bh1);
            }
        }

        // mask + exp2 + pack P
        uint32_t aP[8][2];
#pragma unroll
        for (int j = 0; j < 8; j++) {
            int s0 = j * 8 + (lane & 3) * 2;
#pragma unroll
            for (int e = 0; e < 4; e++) {
                int s_l = s0 + (e & 1);
                int s_g = sj * 64 + s_l;
                int t_g = t_base + (e >> 1) * 8;
                float v = S[j][e] * csc;
                if (mrow[s_l] || (s_g > t_g)) v = -1e9f;
                S[j][e] = fex2(v);
            }
            lsum0 += S[j][0] + S[j][1];
            lsum1 += S[j][2] + S[j][3];
            __half2 h0 = __floats2half2_rn(S[j][0], S[j][1]);
            __half2 h1 = __floats2half2_rn(S[j][2], S[j][3]);
            aP[j][0] = *(uint32_t*)&h0;
            aP[j][1] = *(uint32_t*)&h1;
        }

        // O += P V (single pass)
#pragma unroll
        for (int kc = 0; kc < 4; kc++) {
            uint32_t Af[4] = {aP[2 * kc][0], aP[2 * kc][1],
                              aP[2 * kc + 1][0], aP[2 * kc + 1][1]};
#pragma unroll
            for (int dj = 0; dj < 4; dj++) {
                uint32_t vd = sV + (uint32_t)((kc * 16 + lrow) * AT_PITCH + dj * 16 + lkc) * 2;
                uint32_t tv[4];
                LDSM4T(tv, vd);
                uint32_t b0[2] = {tv[0], tv[1]}, b1[2] = {tv[2], tv[3]};
                mma16816(O[2 * dj],     Af, b0);
                mma16816(O[2 * dj + 1], Af, b1);
            }
        }
        __syncthreads();
    }

    // finalize
    lsum0 += __shfl_xor_sync(0xffffffffu, lsum0, 1);
    lsum0 += __shfl_xor_sync(0xffffffffu, lsum0, 2);
    lsum1 += __shfl_xor_sync(0xffffffffu, lsum1, 1);
    lsum1 += __shfl_xor_sync(0xffffffffu, lsum1, 2);
    float inv0 = 1.0f / lsum0;
    float inv1 = 1.0f / lsum1;

#pragma unroll
    for (int hh = 0; hh < 2; hh++) {
        float inv = hh ? inv1 : inv0;
        size_t orow = (size_t)(b * TT + t_base + hh * 8) * CC + h * DD + (lane & 3) * 2;
#pragma unroll
        for (int j = 0; j < 8; j++) {
            float v0 = O[j][hh * 2 + 0] * inv;
            float v1 = O[j][hh * 2 + 1] * inv;
            *(__half2*)(outp + orow + j * 8) = __floats2half2_rn(v0, v1);
        }
    }
}

// ---------------------------------------------------------------------------
// Fixup: rows t < first_unpadded[b] -> out = mean of V over padded positions.
// ---------------------------------------------------------------------------
__global__ __launch_bounds__(256) void fixup_kernel(
    const __half* __restrict__ qkv,
    const int* __restrict__ mask,
    __half* __restrict__ outp)
{
    int b = blockIdx.x;
    int f = g_fu[b];
    if (f == 0) return;
    int tid = threadIdx.x;
    float sum[4] = {0, 0, 0, 0};
    int cnt = 0;
    for (int s = 0; s < TT; s++) {
        if (mask[b * TT + s]) {
            cnt++;
            size_t base = (size_t)(b * TT + s) * (3 * CC) + 2 * CC + tid * 4;
#pragma unroll
            for (int e = 0; e < 4; e++)
                sum[e] += __half2float(qkv[base + e]);
        }
    }
    float invc = 1.0f / (float)cnt;
    __half mh[4];
#pragma unroll
    for (int e = 0; e < 4; e++) mh[e] = __float2half_rn(sum[e] * invc);
    for (int t = 0; t < f; t++) {
        size_t o = (size_t)(b * TT + t) * CC + tid * 4;
#pragma unroll
        for (int e = 0; e < 4; e++)
            outp[o + e] = mh[e];
    }
}

// ---------------------------------------------------------------------------
// Launch. Side stream: mask + weight transposes, overlapped with LN1/QKV.
// ---------------------------------------------------------------------------
static cudaStream_t s_side = nullptr;
static cudaEvent_t  s_evF = nullptr, s_evM = nullptr, s_evJ = nullptr;

extern "C" void kernel_launch(void* const* d_in, const int* in_sizes, int n_in,
                              void* d_out, int out_size)
{
    const float* x     = (const float*)d_in[0];
    const void*  pmask = d_in[1];
    const float* Wq    = (const float*)d_in[2];
    const float* Wk    = (const float*)d_in[3];
    const float* Wv    = (const float*)d_in[4];
    const float* Wo    = (const float*)d_in[5];
    const float* bo    = (const float*)d_in[6];
    const float* ln1_g = (const float*)d_in[7];
    const float* ln1_b = (const float*)d_in[8];
    const float* ln2_g = (const float*)d_in[9];
    const float* ln2_b = (const float*)d_in[10];
    const float* W1    = (const float*)d_in[11];
    const float* b1    = (const float*)d_in[12];
    const float* W2    = (const float*)d_in[13];
    const float* b2    = (const float*)d_in[14];
    float* out = (float*)d_out;

    void *p_qkv, *p_h, *p_at, *p_h2, *p_f1,
         *p_wq, *p_wo, *p_w1, *p_w2, *p_mask;
    cudaGetSymbolAddress(&p_qkv,  g_qkv);
    cudaGetSymbolAddress(&p_h,    g_h);
    cudaGetSymbolAddress(&p_at,   g_at);
    cudaGetSymbolAddress(&p_h2,   g_h2);
    cudaGetSymbolAddress(&p_f1,   g_f1);
    cudaGetSymbolAddress(&p_wq,   g_wq);
    cudaGetSymbolAddress(&p_wo,   g_wo);
    cudaGetSymbolAddress(&p_w1,   g_w1);
    cudaGetSymbolAddress(&p_w2,   g_w2);
    cudaGetSymbolAddress(&p_mask, g_mask);

    cudaFuncSetAttribute(gemm_mma, cudaFuncAttributeMaxDynamicSharedMemorySize, GEMM_SMEM);
    cudaFuncSetAttribute(attn_mma, cudaFuncAttributeMaxDynamicSharedMemorySize, ATT_SMEM);

    if (!s_side) {
        cudaStreamCreateWithFlags(&s_side, cudaStreamNonBlocking);
        cudaEventCreateWithFlags(&s_evF, cudaEventDisableTiming);
        cudaEventCreateWithFlags(&s_evM, cudaEventDisableTiming);
        cudaEventCreateWithFlags(&s_evJ, cudaEventDisableTiming);
    }

    // ---- fork: mask + weight transposes on the side stream ----
    cudaEventRecord(s_evF, 0);
    cudaStreamWaitEvent(s_side, s_evF, 0);
    fu_init_kernel<<<1, 32, 0, s_side>>>();
    mask_expand_kernel<<<16, 256, 0, s_side>>>(pmask, (int*)p_mask);
    cudaEventRecord(s_evM, s_side);          // mask ready
    tsplit_kernel<<<dim3(CC / 32, CC / 32), dim3(32, 8), 0, s_side>>>(
        Wo, (__half*)p_wo, CC, CC);
    tsplit_kernel<<<dim3(FF / 32, CC / 32), dim3(32, 8), 0, s_side>>>(
        W1, (__half*)p_w1, CC, FF);
    tsplit_kernel<<<dim3(CC / 32, FF / 32), dim3(32, 8), 0, s_side>>>(
        W2, (__half*)p_w2, FF, CC);
    cudaEventRecord(s_evJ, s_side);          // weights ready

    // ---- main stream ----
    pack_qkv_kernel<<<3 * 16 * 32, dim3(32, 8)>>>(Wq, Wk, Wv, (__half*)p_wq);
    ln_kernel<<<MR, 256>>>(x, ln1_g, ln1_b, (__half*)p_h);
    gemm_mma<<<dim3(3 * CC / 256, MR / 128), 256, GEMM_SMEM>>>(
        (__half*)p_h, (__half*)p_wq, nullptr,
        nullptr, (__half*)p_qkv, 3 * CC, CC, 0);

    cudaStreamWaitEvent(0, s_evM, 0);        // mask ready before attention
    attn_mma<<<dim3(TT / 128, BB * HH), 256, ATT_SMEM>>>(
        (const __half*)p_qkv, (const int*)p_mask, (__half*)p_at);
    fixup_kernel<<<BB, 256>>>(
        (const __half*)p_qkv, (const int*)p_mask, (__half*)p_at);

    cudaStreamWaitEvent(0, s_evJ, 0);        // weights ready before Wo/FFN

    // Wo projection (fp16 out, reusing g_h)
    gemm_mma<<<dim3(CC / 256, MR / 128), 256, GEMM_SMEM>>>(
        (__half*)p_at, (__half*)p_wo, bo,
        nullptr, (__half*)p_h, CC, CC, 0);
    // LN2 (fp16 input)
    ln_h_kernel<<<MR, 256>>>((const __half*)p_h, ln2_g, ln2_b, (__half*)p_h2);
    // FFN1 + relu
    gemm_mma<<<dim3(FF / 256, MR / 128), 256, GEMM_SMEM>>>(
        (__half*)p_h2, (__half*)p_w1, b1,
        nullptr, (__half*)p_f1, FF, CC, 1);
    // FFN2 -> d_out
    gemm_mma<<<dim3(CC / 256, MR / 128), 256, GEMM_SMEM>>>(
        (__half*)p_f1, (__half*)p_w2, b2,
        out, nullptr, CC, FF, 0);
}

// round 16
// speedup vs baseline: 2.0153x; 1.0131x over previous
#include <cuda_runtime.h>
#include <cuda_fp16.h>
#include <cstdint>
#include <math.h>

// Problem dims
#define BB 4
#define TT 1024
#define CC 1024
#define HH 16
#define DD 64
#define FF 4096
#define MR 4096   // B*T

// ---------------------------------------------------------------------------
// Scratch (static device globals)
// ---------------------------------------------------------------------------
__device__ __align__(256) __half g_qkv[MR * 3 * CC];
__device__ __align__(256) __half g_h  [MR * CC];   // LN1 out; reused for proj fp16
__device__ __align__(256) __half g_at [MR * CC];
__device__ __align__(256) __half g_h2 [MR * CC];
__device__ __align__(256) __half g_f1 [MR * FF];
__device__ __align__(256) __half g_wq [3 * CC * CC];
__device__ __align__(256) __half g_wo [CC * CC];
__device__ __align__(256) __half g_w1 [FF * CC];
__device__ __align__(256) __half g_w2 [CC * FF];
__device__ int g_mask[MR];
__device__ int g_fu[BB];

// ---------------------------------------------------------------------------
// Helpers
// ---------------------------------------------------------------------------
__device__ __forceinline__ uint32_t smem_u32(const void* p) {
    uint32_t a;
    asm("{ .reg .u64 t; cvta.to.shared.u64 t, %1; cvt.u32.u64 %0, t; }" : "=r"(a) : "l"(p));
    return a;
}
__device__ __forceinline__ void cp16(uint32_t s, const void* g) {
    asm volatile("cp.async.cg.shared.global [%0], [%1], 16;" :: "r"(s), "l"(g));
}
#define CP_COMMIT() asm volatile("cp.async.commit_group;" ::: "memory")
#define CP_WAIT3()  asm volatile("cp.async.wait_group 3;"  ::: "memory")
#define CP_WAIT1()  asm volatile("cp.async.wait_group 1;"  ::: "memory")
#define CP_WAIT0()  asm volatile("cp.async.wait_group 0;"  ::: "memory")

#define LDSM4(r, addr) \
    asm volatile("ldmatrix.sync.aligned.m8n8.x4.shared.b16 {%0,%1,%2,%3}, [%4];" \
        : "=r"((r)[0]), "=r"((r)[1]), "=r"((r)[2]), "=r"((r)[3]) : "r"(addr))
#define LDSM4T(r, addr) \
    asm volatile("ldmatrix.sync.aligned.m8n8.x4.trans.shared.b16 {%0,%1,%2,%3}, [%4];" \
        : "=r"((r)[0]), "=r"((r)[1]), "=r"((r)[2]), "=r"((r)[3]) : "r"(addr))

__device__ __forceinline__ void mma16816(float* c, const uint32_t* a, const uint32_t* b) {
    asm volatile("mma.sync.aligned.m16n8k16.row.col.f32.f16.f16.f32 "
        "{%0,%1,%2,%3}, {%4,%5,%6,%7}, {%8,%9}, {%0,%1,%2,%3};"
        : "+f"(c[0]), "+f"(c[1]), "+f"(c[2]), "+f"(c[3])
        : "r"(a[0]), "r"(a[1]), "r"(a[2]), "r"(a[3]), "r"(b[0]), "r"(b[1]));
}

__device__ __forceinline__ float fex2(float x) {
    float r;
    asm("ex2.approx.ftz.f32 %0, %1;" : "=f"(r) : "f"(x));
    return r;
}

// ---------------------------------------------------------------------------
// g_fu init (runs before mask_expand on side stream)
// ---------------------------------------------------------------------------
__global__ void fu_init_kernel()
{
    if (threadIdx.x < BB) g_fu[threadIdx.x] = TT;
}

// ---------------------------------------------------------------------------
// Mask classify + expand + first-unpadded per batch (16 blocks)
// ---------------------------------------------------------------------------
__global__ void mask_expand_kernel(const void* __restrict__ pm, int* __restrict__ out)
{
    int tid = threadIdx.x;
    const unsigned* w = (const unsigned*)pm;
    int li = 0, lf = 0;
    for (int i = tid; i < 1024; i += 256) {
        unsigned v = w[i];
        li |= (v > 1u);
        lf |= (v != 0u && v != 0x3F800000u);
    }
    int not_int = __syncthreads_or(li);
    int not_flt = __syncthreads_or(lf);
    int cls = (!not_int) ? 0 : ((!not_flt) ? 1 : 2);
    int i = blockIdx.x * 256 + tid;
    int m;
    if (cls == 0)      m = (((const int*)pm)[i] != 0);
    else if (cls == 1) m = (((const float*)pm)[i] != 0.0f);
    else               m = (((const unsigned char*)pm)[i] != 0);
    out[i] = m;
    if (!m) atomicMin(&g_fu[i >> 10], i & 1023);
}

// ---------------------------------------------------------------------------
// Tiled pack of Wq/Wk/Wv (H,C,D) -> transposed (3C, C) fp16, coalesced.
// ---------------------------------------------------------------------------
__global__ void pack_qkv_kernel(const float* __restrict__ Wq,
                                const float* __restrict__ Wk,
                                const float* __restrict__ Wv,
                                __half* __restrict__ oh)
{
    __shared__ float t[32][65];
    int bid = blockIdx.x;
    int wsel = bid >> 9;
    int rem = bid & 511;
    int h = rem >> 5, ct = rem & 31;
    const float* W = (wsel == 0) ? Wq : (wsel == 1) ? Wk : Wv;
    int c0 = ct * 32;
    int x = threadIdx.x, y = threadIdx.y;   // 32 x 8

    const float* src = W + ((size_t)h * CC + c0) * DD;
#pragma unroll
    for (int i = 0; i < 4; i++) {
        int cc = y + i * 8;
        t[cc][x]      = src[(size_t)cc * DD + x];
        t[cc][x + 32] = src[(size_t)cc * DD + x + 32];
    }
    __syncthreads();

    size_t obase = ((size_t)wsel * CC + h * DD) * CC + c0;
#pragma unroll
    for (int i = 0; i < 8; i++) {
        int d = y + i * 8;
        oh[obase + (size_t)d * CC + x] = __float2half_rn(t[x][d]);
    }
}

// ---------------------------------------------------------------------------
// Tiled transpose: in (R, Cn) fp32 -> out (Cn, R) fp16
// ---------------------------------------------------------------------------
__global__ void tsplit_kernel(const float* __restrict__ in,
                              __half* __restrict__ oh,
                              int R, int Cn)
{
    __shared__ float t[32][33];
    int c0 = blockIdx.x * 32, r0 = blockIdx.y * 32;
    int x = threadIdx.x, y = threadIdx.y;
#pragma unroll
    for (int i = 0; i < 32; i += 8)
        t[y + i][x] = in[(size_t)(r0 + y + i) * Cn + c0 + x];
    __syncthreads();
#pragma unroll
    for (int i = 0; i < 32; i += 8)
        oh[(size_t)(c0 + y + i) * R + r0 + x] = __float2half_rn(t[x][y + i]);
}

// ---------------------------------------------------------------------------
// LayerNorm (fp32 input) -> fp16
// ---------------------------------------------------------------------------
__global__ __launch_bounds__(256) void ln_kernel(const float* __restrict__ x,
                                                 const float* __restrict__ g,
                                                 const float* __restrict__ b,
                                                 __half* __restrict__ oh)
{
    int row = blockIdx.x, tid = threadIdx.x;
    const float* xr = x + (size_t)row * CC;
    float v[4];
    float s = 0.f, ss = 0.f;
#pragma unroll
    for (int i = 0; i < 4; i++) {
        v[i] = xr[tid + i * 256];
        s += v[i];
        ss += v[i] * v[i];
    }
#pragma unroll
    for (int o = 16; o; o >>= 1) {
        s  += __shfl_xor_sync(0xffffffffu, s,  o);
        ss += __shfl_xor_sync(0xffffffffu, ss, o);
    }
    __shared__ float ws[8], wss[8];
    __shared__ float s_m, s_r;
    int wid = tid >> 5;
    if ((tid & 31) == 0) { ws[wid] = s; wss[wid] = ss; }
    __syncthreads();
    if (tid == 0) {
        float S = 0.f, SS = 0.f;
        for (int i = 0; i < 8; i++) { S += ws[i]; SS += wss[i]; }
        float m = S * (1.0f / CC);
        float var = SS * (1.0f / CC) - m * m;
        s_m = m;
        s_r = rsqrtf(var + 1e-5f);
    }
    __syncthreads();
    float m = s_m, r = s_r;
#pragma unroll
    for (int i = 0; i < 4; i++) {
        int c = tid + i * 256;
        float o = (v[i] - m) * r * g[c] + b[c];
        oh[(size_t)row * CC + c] = __float2half_rn(o);
    }
}

// ---------------------------------------------------------------------------
// LayerNorm (fp16 input) -> fp16
// ---------------------------------------------------------------------------
__global__ __launch_bounds__(256) void ln_h_kernel(const __half* __restrict__ x,
                                                   const float* __restrict__ g,
                                                   const float* __restrict__ b,
                                                   __half* __restrict__ oh)
{
    int row = blockIdx.x, tid = threadIdx.x;
    const __half* xr = x + (size_t)row * CC;
    float v[4];
    float s = 0.f, ss = 0.f;
#pragma unroll
    for (int i = 0; i < 4; i++) {
        v[i] = __half2float(xr[tid + i * 256]);
        s += v[i];
        ss += v[i] * v[i];
    }
#pragma unroll
    for (int o = 16; o; o >>= 1) {
        s  += __shfl_xor_sync(0xffffffffu, s,  o);
        ss += __shfl_xor_sync(0xffffffffu, ss, o);
    }
    __shared__ float ws[8], wss[8];
    __shared__ float s_m, s_r;
    int wid = tid >> 5;
    if ((tid & 31) == 0) { ws[wid] = s; wss[wid] = ss; }
    __syncthreads();
    if (tid == 0) {
        float S = 0.f, SS = 0.f;
        for (int i = 0; i < 8; i++) { S += ws[i]; SS += wss[i]; }
        float m = S * (1.0f / CC);
        float var = SS * (1.0f / CC) - m * m;
        s_m = m;
        s_r = rsqrtf(var + 1e-5f);
    }
    __syncthreads();
    float m = s_m, r = s_r;
#pragma unroll
    for (int i = 0; i < 4; i++) {
        int c = tid + i * 256;
        float o = (v[i] - m) * r * g[c] + b[c];
        oh[(size_t)row * CC + c] = __float2half_rn(o);
    }
}

// ---------------------------------------------------------------------------
// fp16 1-pass GEMM (validated R14 config, untouched)
// ---------------------------------------------------------------------------
#define PITCH 72
#define A_TILE_B (128 * PITCH * 2)
#define B_TILE_B (256 * PITCH * 2)
#define STAGE_B (A_TILE_B + B_TILE_B)
#define NSTAGE 4
#define GEMM_SMEM (NSTAGE * STAGE_B)

__global__ __launch_bounds__(256, 1) void gemm_mma(
    const __half* __restrict__ Ah,
    const __half* __restrict__ Bh,
    const float* __restrict__ bias,
    float* __restrict__ outF,
    __half* __restrict__ outH,
    int Ntot, int Ktot, int relu)
{
    extern __shared__ __align__(128) char smem[];
    const uint32_t sb0 = smem_u32(smem);
    int tid = threadIdx.x, lane = tid & 31, w = tid >> 5;
    int bm = blockIdx.y * 128, bn = blockIdx.x * 256;
    int wm = (w & 1) * 64, wn = (w >> 1) * 64;
    int nk = Ktot >> 6;

    float acc[4][8][4];
#pragma unroll
    for (int i = 0; i < 4; i++)
#pragma unroll
        for (int j = 0; j < 8; j++)
#pragma unroll
            for (int e = 0; e < 4; e++) acc[i][j][e] = 0.0f;

    auto load_stage = [&](int st, int kc) {
        uint32_t sb = sb0 + st * STAGE_B;
#pragma unroll
        for (int i = 0; i < 12; i++) {
            int idx = tid + i * 256;
            int c = (idx & 7) * 8;
            if (idx < 1024) {
                int r = idx >> 3;
                cp16(sb + (uint32_t)(r * PITCH + c) * 2,
                     Ah + (size_t)(bm + r) * Ktot + kc + c);
            } else {
                int r = (idx - 1024) >> 3;
                cp16(sb + A_TILE_B + (uint32_t)(r * PITCH + c) * 2,
                     Bh + (size_t)(bn + r) * Ktot + kc + c);
            }
        }
    };

    load_stage(0, 0);  CP_COMMIT();
    load_stage(1, 64); CP_COMMIT();
    load_stage(2, 128); CP_COMMIT();

    int lrow = lane & 15;
    int lk = (lane >> 4) * 8;

    for (int kc = 0; kc < nk; kc++) {
        if (kc + 3 < nk) {
            load_stage((kc + 3) & 3, (kc + 3) * 64);
            CP_COMMIT();
            CP_WAIT3();
        } else {
            CP_WAIT0();
        }
        __syncthreads();

        uint32_t sb = sb0 + (kc & 3) * STAGE_B;
#pragma unroll
        for (int ks = 0; ks < 4; ks++) {
            int k0 = ks * 16;
            uint32_t ah[4][4], bh[8][2];
#pragma unroll
            for (int i = 0; i < 4; i++) {
                uint32_t ad = sb + (uint32_t)((wm + i * 16 + lrow) * PITCH + k0 + lk) * 2;
                LDSM4(ah[i], ad);
            }
#pragma unroll
            for (int jj = 0; jj < 4; jj++) {
                uint32_t bd = sb + A_TILE_B +
                              (uint32_t)((wn + jj * 16 + lrow) * PITCH + k0 + lk) * 2;
                uint32_t t[4];
                LDSM4(t, bd);
                bh[jj * 2][0] = t[0]; bh[jj * 2][1] = t[2];
                bh[jj * 2 + 1][0] = t[1]; bh[jj * 2 + 1][1] = t[3];
            }
#pragma unroll
            for (int i = 0; i < 4; i++)
#pragma unroll
                for (int j = 0; j < 8; j++)
                    mma16816(acc[i][j], ah[i], bh[j]);
        }
        __syncthreads();
    }

#pragma unroll
    for (int i = 0; i < 4; i++) {
        int r0 = bm + wm + i * 16 + (lane >> 2);
#pragma unroll
        for (int j = 0; j < 8; j++) {
            int c = bn + wn + j * 8 + (lane & 3) * 2;
            float bx0 = bias ? bias[c] : 0.0f;
            float bx1 = bias ? bias[c + 1] : 0.0f;
#pragma unroll
            for (int hh = 0; hh < 2; hh++) {
                int r = r0 + hh * 8;
                float v0 = acc[i][j][hh * 2 + 0] + bx0;
                float v1 = acc[i][j][hh * 2 + 1] + bx1;
                if (relu) { v0 = fmaxf(v0, 0.0f); v1 = fmaxf(v1, 0.0f); }
                size_t o = (size_t)r * Ntot + c;
                if (outF) {
                    outF[o] = v0;
                    outF[o + 1] = v1;
                } else {
                    *(__half2*)(outH + o) = __floats2half2_rn(v0, v1);
                }
            }
        }
    }
}

// ---------------------------------------------------------------------------
// fp16 flash attention: single-pass QK, single-pass PV.
// CTA 256 thr (8 warps), q-tile 128, K/V staged in 128-row chunks
// (double-buffered), two 64-column compute passes per stage (no mid syncs).
// Causal-only sweep; heavy blocks first.
// ---------------------------------------------------------------------------
#define AT_PITCH 72
#define AQ_TILEB (128 * AT_PITCH * 2)       // 18432
#define AKV_TILEB (128 * AT_PITCH * 2)      // 36864 (128-row stage, K or V)
#define SMASK_OFF (AQ_TILEB + 4 * AKV_TILEB)       // 165888
#define ATT_SMEM (SMASK_OFF + 2 * 128 * 4)         // 166912

__global__ __launch_bounds__(256) void attn_mma(
    const __half* __restrict__ qkv,
    const int* __restrict__ mask,
    __half* __restrict__ outp)
{
    extern __shared__ __align__(128) char smem[];
    const uint32_t sb = smem_u32(smem);
    const uint32_t sQ = sb;

    int qi = (int)gridDim.x - 1 - (int)blockIdx.x;   // heavy blocks first
    int bh = blockIdx.y;
    int b = bh >> 4, h = bh & 15;
    int tid = threadIdx.x, lane = tid & 31, w = tid >> 5;
    int wq = w * 16;
    int lrow = lane & 15, lkc = (lane >> 4) * 8;

    const size_t rowbase = (size_t)(b * TT) * (3 * CC) + h * DD;
    const int* gmask = mask + b * TT;
    int* smask = (int*)(smem + SMASK_OFF);

    // Q tile
#pragma unroll
    for (int i = 0; i < 4; i++) {
        int idx = tid + i * 256;
        int r = idx >> 3, ch = (idx & 7) * 8;
        uint32_t so = (uint32_t)(r * AT_PITCH + ch) * 2;
        size_t go = rowbase + (size_t)(qi * 128 + r) * (3 * CC) + ch;
        cp16(sQ + so, qkv + go);
    }

    // stage loader: 128 rows of K + 128 rows of V + 128 mask ints
    auto load_stage = [&](int sj) {
        int st = sj & 1;
        uint32_t base = sb + AQ_TILEB + st * (2 * AKV_TILEB);
#pragma unroll
        for (int i = 0; i < 8; i++) {
            int idx = tid + i * 256;          // 0..2047
            int tile = idx >> 10;             // 0:K 1:V
            int rem = idx & 1023;
            int r = rem >> 3, ch = (rem & 7) * 8;
            uint32_t so = base + tile * AKV_TILEB + (uint32_t)(r * AT_PITCH + ch) * 2;
            size_t gk = rowbase + (size_t)(sj * 128 + r) * (3 * CC) + CC + ch;
            if (tile == 0) cp16(so, qkv + gk);
            else           cp16(so, qkv + gk + CC);
        }
        if (tid < 32)
            cp16(sb + SMASK_OFF + st * 512 + tid * 16, gmask + sj * 128 + tid * 4);
    };

    int ns = qi + 1;
    load_stage(0);
    CP_COMMIT();

    float O[8][4];
#pragma unroll
    for (int j = 0; j < 8; j++)
#pragma unroll
        for (int e = 0; e < 4; e++) O[j][e] = 0.0f;
    float lsum0 = 0.0f, lsum1 = 0.0f;

    const float csc = 0.0450842200f;   // log2(e) / 32
    const int t_base = qi * 128 + wq + (lane >> 2);

    for (int sj = 0; sj < ns; sj++) {
        int cur = sj & 1;
        if (sj + 1 < ns) {
            load_stage(sj + 1);
            CP_COMMIT();
            CP_WAIT1();
        } else {
            CP_WAIT0();
        }
        __syncthreads();

        uint32_t kvb = sb + AQ_TILEB + cur * (2 * AKV_TILEB);
        const int* mrow = smask + cur * 128;

        // two 64-column halves per 128-row stage (same order as 64-stages)
#pragma unroll
        for (int half = 0; half < 2; half++) {
            uint32_t sK = kvb + (uint32_t)(half * 64) * AT_PITCH * 2;
            uint32_t sV = kvb + AKV_TILEB + (uint32_t)(half * 64) * AT_PITCH * 2;
            const int* mh_ = mrow + half * 64;
            int scol0 = sj * 128 + half * 64;

            // S = Q K^T
            float S[8][4];
#pragma unroll
            for (int j = 0; j < 8; j++)
#pragma unroll
                for (int e = 0; e < 4; e++) S[j][e] = 0.0f;

#pragma unroll
            for (int ks = 0; ks < 4; ks++) {
                uint32_t qa[4];
                uint32_t ad = sQ + (uint32_t)((wq + lrow) * AT_PITCH + ks * 16 + lkc) * 2;
                LDSM4(qa, ad);
#pragma unroll
                for (int nj = 0; nj < 4; nj++) {
                    uint32_t bd = sK + (uint32_t)((nj * 16 + lrow) * AT_PITCH + ks * 16 + lkc) * 2;
                    uint32_t th[4];
                    LDSM4(th, bd);
                    uint32_t bh0[2] = {th[0], th[2]}, bh1[2] = {th[1], th[3]};
                    mma16816(S[2 * nj],     qa, bh0);
                    mma16816(S[2 * nj + 1], qa, bh1);
                }
            }

            // mask + exp2 + pack P
            uint32_t aP[8][2];
#pragma unroll
            for (int j = 0; j < 8; j++) {
                int s0 = j * 8 + (lane & 3) * 2;
#pragma unroll
                for (int e = 0; e < 4; e++) {
                    int s_l = s0 + (e & 1);
                    int s_g = scol0 + s_l;
                    int t_g = t_base + (e >> 1) * 8;
                    float v = S[j][e] * csc;
                    if (mh_[s_l] || (s_g > t_g)) v = -1e9f;
                    S[j][e] = fex2(v);
                }
                lsum0 += S[j][0] + S[j][1];
                lsum1 += S[j][2] + S[j][3];
                __half2 h0 = __floats2half2_rn(S[j][0], S[j][1]);
                __half2 h1 = __floats2half2_rn(S[j][2], S[j][3]);
                aP[j][0] = *(uint32_t*)&h0;
                aP[j][1] = *(uint32_t*)&h1;
            }

            // O += P V
#pragma unroll
            for (int kc = 0; kc < 4; kc++) {
                uint32_t Af[4] = {aP[2 * kc][0], aP[2 * kc][1],
                                  aP[2 * kc + 1][0], aP[2 * kc + 1][1]};
#pragma unroll
                for (int dj = 0; dj < 4; dj++) {
                    uint32_t vd = sV + (uint32_t)((kc * 16 + lrow) * AT_PITCH + dj * 16 + lkc) * 2;
                    uint32_t tv[4];
                    LDSM4T(tv, vd);
                    uint32_t b0[2] = {tv[0], tv[1]}, b1[2] = {tv[2], tv[3]};
                    mma16816(O[2 * dj],     Af, b0);
                    mma16816(O[2 * dj + 1], Af, b1);
                }
            }
        }
        __syncthreads();
    }

    // finalize
    lsum0 += __shfl_xor_sync(0xffffffffu, lsum0, 1);
    lsum0 += __shfl_xor_sync(0xffffffffu, lsum0, 2);
    lsum1 += __shfl_xor_sync(0xffffffffu, lsum1, 1);
    lsum1 += __shfl_xor_sync(0xffffffffu, lsum1, 2);
    float inv0 = 1.0f / lsum0;
    float inv1 = 1.0f / lsum1;

#pragma unroll
    for (int hh = 0; hh < 2; hh++) {
        float inv = hh ? inv1 : inv0;
        size_t orow = (size_t)(b * TT + t_base + hh * 8) * CC + h * DD + (lane & 3) * 2;
#pragma unroll
        for (int j = 0; j < 8; j++) {
            float v0 = O[j][hh * 2 + 0] * inv;
            float v1 = O[j][hh * 2 + 1] * inv;
            *(__half2*)(outp + orow + j * 8) = __floats2half2_rn(v0, v1);
        }
    }
}

// ---------------------------------------------------------------------------
// Fixup: rows t < first_unpadded[b] -> out = mean of V over padded positions.
// ---------------------------------------------------------------------------
__global__ __launch_bounds__(256) void fixup_kernel(
    const __half* __restrict__ qkv,
    const int* __restrict__ mask,
    __half* __restrict__ outp)
{
    int b = blockIdx.x;
    int f = g_fu[b];
    if (f == 0) return;
    int tid = threadIdx.x;
    float sum[4] = {0, 0, 0, 0};
    int cnt = 0;
    for (int s = 0; s < TT; s++) {
        if (mask[b * TT + s]) {
            cnt++;
            size_t base = (size_t)(b * TT + s) * (3 * CC) + 2 * CC + tid * 4;
#pragma unroll
            for (int e = 0; e < 4; e++)
                sum[e] += __half2float(qkv[base + e]);
        }
    }
    float invc = 1.0f / (float)cnt;
    __half mh[4];
#pragma unroll
    for (int e = 0; e < 4; e++) mh[e] = __float2half_rn(sum[e] * invc);
    for (int t = 0; t < f; t++) {
        size_t o = (size_t)(b * TT + t) * CC + tid * 4;
#pragma unroll
        for (int e = 0; e < 4; e++)
            outp[o + e] = mh[e];
    }
}

// ---------------------------------------------------------------------------
// Launch. Side stream: mask + weight transposes, overlapped with LN1/QKV.
// ---------------------------------------------------------------------------
static cudaStream_t s_side = nullptr;
static cudaEvent_t  s_evF = nullptr, s_evM = nullptr, s_evJ = nullptr;

extern "C" void kernel_launch(void* const* d_in, const int* in_sizes, int n_in,
                              void* d_out, int out_size)
{
    const float* x     = (const float*)d_in[0];
    const void*  pmask = d_in[1];
    const float* Wq    = (const float*)d_in[2];
    const float* Wk    = (const float*)d_in[3];
    const float* Wv    = (const float*)d_in[4];
    const float* Wo    = (const float*)d_in[5];
    const float* bo    = (const float*)d_in[6];
    const float* ln1_g = (const float*)d_in[7];
    const float* ln1_b = (const float*)d_in[8];
    const float* ln2_g = (const float*)d_in[9];
    const float* ln2_b = (const float*)d_in[10];
    const float* W1    = (const float*)d_in[11];
    const float* b1    = (const float*)d_in[12];
    const float* W2    = (const float*)d_in[13];
    const float* b2    = (const float*)d_in[14];
    float* out = (float*)d_out;

    void *p_qkv, *p_h, *p_at, *p_h2, *p_f1,
         *p_wq, *p_wo, *p_w1, *p_w2, *p_mask;
    cudaGetSymbolAddress(&p_qkv,  g_qkv);
    cudaGetSymbolAddress(&p_h,    g_h);
    cudaGetSymbolAddress(&p_at,   g_at);
    cudaGetSymbolAddress(&p_h2,   g_h2);
    cudaGetSymbolAddress(&p_f1,   g_f1);
    cudaGetSymbolAddress(&p_wq,   g_wq);
    cudaGetSymbolAddress(&p_wo,   g_wo);
    cudaGetSymbolAddress(&p_w1,   g_w1);
    cudaGetSymbolAddress(&p_w2,   g_w2);
    cudaGetSymbolAddress(&p_mask, g_mask);

    cudaFuncSetAttribute(gemm_mma, cudaFuncAttributeMaxDynamicSharedMemorySize, GEMM_SMEM);
    cudaFuncSetAttribute(attn_mma, cudaFuncAttributeMaxDynamicSharedMemorySize, ATT_SMEM);

    if (!s_side) {
        cudaStreamCreateWithFlags(&s_side, cudaStreamNonBlocking);
        cudaEventCreateWithFlags(&s_evF, cudaEventDisableTiming);
        cudaEventCreateWithFlags(&s_evM, cudaEventDisableTiming);
        cudaEventCreateWithFlags(&s_evJ, cudaEventDisableTiming);
    }

    // ---- fork: mask + weight transposes on the side stream ----
    cudaEventRecord(s_evF, 0);
    cudaStreamWaitEvent(s_side, s_evF, 0);
    fu_init_kernel<<<1, 32, 0, s_side>>>();
    mask_expand_kernel<<<16, 256, 0, s_side>>>(pmask, (int*)p_mask);
    cudaEventRecord(s_evM, s_side);          // mask ready
    tsplit_kernel<<<dim3(CC / 32, CC / 32), dim3(32, 8), 0, s_side>>>(
        Wo, (__half*)p_wo, CC, CC);
    tsplit_kernel<<<dim3(FF / 32, CC / 32), dim3(32, 8), 0, s_side>>>(
        W1, (__half*)p_w1, CC, FF);
    tsplit_kernel<<<dim3(CC / 32, FF / 32), dim3(32, 8), 0, s_side>>>(
        W2, (__half*)p_w2, FF, CC);
    cudaEventRecord(s_evJ, s_side);          // weights ready

    // ---- main stream ----
    pack_qkv_kernel<<<3 * 16 * 32, dim3(32, 8)>>>(Wq, Wk, Wv, (__half*)p_wq);
    ln_kernel<<<MR, 256>>>(x, ln1_g, ln1_b, (__half*)p_h);
    gemm_mma<<<dim3(3 * CC / 256, MR / 128), 256, GEMM_SMEM>>>(
        (__half*)p_h, (__half*)p_wq, nullptr,
        nullptr, (__half*)p_qkv, 3 * CC, CC, 0);

    cudaStreamWaitEvent(0, s_evM, 0);        // mask ready before attention
    attn_mma<<<dim3(TT / 128, BB * HH), 256, ATT_SMEM>>>(
        (const __half*)p_qkv, (const int*)p_mask, (__half*)p_at);
    fixup_kernel<<<BB, 256>>>(
        (const __half*)p_qkv, (const int*)p_mask, (__half*)p_at);

    cudaStreamWaitEvent(0, s_evJ, 0);        // weights ready before Wo/FFN

    // Wo projection (fp16 out, reusing g_h)
    gemm_mma<<<dim3(CC / 256, MR / 128), 256, GEMM_SMEM>>>(
        (__half*)p_at, (__half*)p_wo, bo,
        nullptr, (__half*)p_h, CC, CC, 0);
    // LN2 (fp16 input)
    ln_h_kernel<<<MR, 256>>>((const __half*)p_h, ln2_g, ln2_b, (__half*)p_h2);
    // FFN1 + relu
    gemm_mma<<<dim3(FF / 256, MR / 128), 256, GEMM_SMEM>>>(
        (__half*)p_h2, (__half*)p_w1, b1,
        nullptr, (__half*)p_f1, FF, CC, 1);
    // FFN2 -> d_out
    gemm_mma<<<dim3(CC / 256, MR / 128), 256, GEMM_SMEM>>>(
        (__half*)p_f1, (__half*)p_w2, b2,
        out, nullptr, CC, FF, 0);
}